// round 5
// baseline (speedup 1.0000x reference)
#include <cuda_runtime.h>
#include <math.h>

#define B_ 4
#define C_ 192
#define H_ 192
#define W_ 192
#define HW_ (H_*W_)
#define HEADS 6

// ---------------- scratch (device globals: allocation-free per harness rules) ----
__device__ float g_kv [(size_t)B_*2*C_*HW_];   // after 1x1 conv      (226 MB)
__device__ float g_kvd[(size_t)B_*2*C_*HW_];   // after depthwise: [k | v]
__device__ float g_q  [(size_t)B_*C_*HW_];     // q conv output       (113 MB)
__device__ float g_invq[B_*C_];
__device__ float g_invk[B_*C_];
__device__ float g_gram[B_*HEADS*32*32];
__device__ float g_weff[(size_t)B_*C_*C_];     // proj_w @ blockdiag(attn), per batch

// ---------------- generic tiled SGEMM: Y[b] = A[b] (MxK) * X[b] (K x HW_) --------
// BM=BN=64, BK=16, 256 threads, 4x4 per-thread tile. N stride hardwired to HW_.
__global__ __launch_bounds__(256) void gemm64(
    const float* __restrict__ A, size_t aStride,
    const float* __restrict__ X, size_t xStride,
    float* __restrict__ Y, size_t yStride, int K)
{
    __shared__ float sA[16][68];
    __shared__ float sB[16][68];
    int tid = threadIdx.x;
    int n0 = blockIdx.x * 64;
    int m0 = blockIdx.y * 64;
    const float* Ab = A + (size_t)blockIdx.z * aStride;
    const float* Xb = X + (size_t)blockIdx.z * xStride;
    float*       Yb = Y + (size_t)blockIdx.z * yStride;
    int ty = tid >> 4, tx = tid & 15;
    int ar  = tid >> 2;           // 0..63 (A row within tile)
    int akq = (tid & 3) << 2;     // 0,4,8,12 (A k quad)
    int xk  = tid >> 4;           // 0..15  (X k row)
    int xn  = (tid & 15) << 2;    // 0..60  (X n quad)
    float acc[4][4] = {};
    for (int k0 = 0; k0 < K; k0 += 16) {
        float4 av = *reinterpret_cast<const float4*>(&Ab[(size_t)(m0 + ar)*K + k0 + akq]);
        float4 xv = *reinterpret_cast<const float4*>(&Xb[(size_t)(k0 + xk)*HW_ + n0 + xn]);
        sA[akq+0][ar] = av.x; sA[akq+1][ar] = av.y;
        sA[akq+2][ar] = av.z; sA[akq+3][ar] = av.w;
        *reinterpret_cast<float4*>(&sB[xk][xn]) = xv;
        __syncthreads();
        #pragma unroll
        for (int kk = 0; kk < 16; kk++) {
            float4 a  = *reinterpret_cast<const float4*>(&sA[kk][ty<<2]);
            float4 bb = *reinterpret_cast<const float4*>(&sB[kk][tx<<2]);
            float aa[4] = {a.x, a.y, a.z, a.w};
            float bv[4] = {bb.x, bb.y, bb.z, bb.w};
            #pragma unroll
            for (int i = 0; i < 4; i++)
                #pragma unroll
                for (int j = 0; j < 4; j++)
                    acc[i][j] += aa[i] * bv[j];
        }
        __syncthreads();
    }
    #pragma unroll
    for (int i = 0; i < 4; i++) {
        float4 o = make_float4(acc[i][0], acc[i][1], acc[i][2], acc[i][3]);
        *reinterpret_cast<float4*>(
            &Yb[(size_t)(m0 + (ty<<2) + i)*HW_ + n0 + (tx<<2)]) = o;
    }
}

// ---------------- 3x3 dense conv (SAME): q = q_w * x --------------------------
// block = 64 out-channels x 64 x-pixels (one row segment); ic chunks of 8.
__global__ __launch_bounds__(256) void conv3x3(
    const float* __restrict__ x, const float* __restrict__ w, float* __restrict__ y)
{
    const int tilesX = W_ / 64;                 // 3
    int yrow = blockIdx.x / tilesX;
    int x0   = (blockIdx.x % tilesX) * 64;
    int oc0  = blockIdx.y * 64;
    int b    = blockIdx.z;
    __shared__ float sW[8][9][64];
    __shared__ float sX[8][3][72];
    int tid = threadIdx.x;
    int ty = tid >> 4, tx = tid & 15;
    float acc[4][4] = {};
    for (int ic0 = 0; ic0 < C_; ic0 += 8) {
        // weights: 64 oc x 8 ic x 9 taps
        for (int l = tid; l < 64*8*9; l += 256) {
            int oc  = l / 72;
            int rem = l % 72;
            sW[rem/9][rem%9][oc] = w[(size_t)(oc0+oc)*(C_*9) + ic0*9 + rem];
        }
        // input halo: 8 ic x 3 rows x 66 px
        for (int l = tid; l < 8*3*66; l += 256) {
            int ic  = l / 198;
            int rem = l - ic*198;
            int dy  = rem / 66;
            int xi  = rem - dy*66;
            int gy  = yrow + dy - 1;
            int gx  = x0 + xi - 1;
            float v = 0.f;
            if (gy >= 0 && gy < H_ && (unsigned)gx < (unsigned)W_)
                v = x[((size_t)(b*C_ + ic0+ic)*H_ + gy)*W_ + gx];
            sX[ic][dy][xi] = v;
        }
        __syncthreads();
        for (int ic = 0; ic < 8; ic++) {
            #pragma unroll
            for (int ky = 0; ky < 3; ky++) {
                float xs[6];
                #pragma unroll
                for (int t = 0; t < 6; t++) xs[t] = sX[ic][ky][(tx<<2) + t];
                #pragma unroll
                for (int kx = 0; kx < 3; kx++) {
                    float wv[4];
                    #pragma unroll
                    for (int i = 0; i < 4; i++) wv[i] = sW[ic][ky*3+kx][(ty<<2)+i];
                    #pragma unroll
                    for (int i = 0; i < 4; i++)
                        #pragma unroll
                        for (int j = 0; j < 4; j++)
                            acc[i][j] += wv[i] * xs[j+kx];
                }
            }
        }
        __syncthreads();
    }
    #pragma unroll
    for (int i = 0; i < 4; i++) {
        float4 o = make_float4(acc[i][0], acc[i][1], acc[i][2], acc[i][3]);
        *reinterpret_cast<float4*>(
            &y[((size_t)(b*C_ + oc0 + (ty<<2) + i)*H_ + yrow)*W_ + x0 + (tx<<2)]) = o;
    }
}

// ---------------- depthwise 3x3 (SAME), groups = 2C ---------------------------
__global__ void dwconv3x3(const float* __restrict__ in, const float* __restrict__ w,
                          float* __restrict__ out)
{
    size_t idx = (size_t)blockIdx.x * 256 + threadIdx.x;
    const size_t total = (size_t)B_*2*C_*HW_;
    if (idx >= total) return;
    int n  = (int)(idx % HW_);
    int ch = (int)((idx / HW_) % (2*C_));
    int px = n % W_, py = n / W_;
    const float* base = in + (idx - n);
    float s = 0.f;
    #pragma unroll
    for (int ky = 0; ky < 3; ky++) {
        int gy = py + ky - 1;
        if ((unsigned)gy >= (unsigned)H_) continue;
        #pragma unroll
        for (int kx = 0; kx < 3; kx++) {
            int gx = px + kx - 1;
            if ((unsigned)gx >= (unsigned)W_) continue;
            s += w[ch*9 + ky*3 + kx] * base[(size_t)gy*W_ + gx];
        }
    }
    out[idx] = s;
}

// ---------------- 1/max(||row||,eps) over HW per (b,c) ------------------------
__global__ __launch_bounds__(256) void invnorm(const float* __restrict__ src,
                                               int chanPerB, float* __restrict__ dst)
{
    int bc = blockIdx.x;
    int b = bc / C_, c = bc % C_;
    const float4* p = reinterpret_cast<const float4*>(src + ((size_t)b*chanPerB + c)*HW_);
    float ss = 0.f;
    for (int i = threadIdx.x; i < HW_/4; i += 256) {
        float4 v = p[i];
        ss += v.x*v.x + v.y*v.y + v.z*v.z + v.w*v.w;
    }
    #pragma unroll
    for (int off = 16; off; off >>= 1) ss += __shfl_xor_sync(0xffffffff, ss, off);
    __shared__ float red[8];
    if ((threadIdx.x & 31) == 0) red[threadIdx.x >> 5] = ss;
    __syncthreads();
    if (threadIdx.x == 0) {
        float t = 0.f;
        #pragma unroll
        for (int i = 0; i < 8; i++) t += red[i];
        float nrm = sqrtf(t);
        dst[bc] = 1.f / fmaxf(nrm, 1e-12f);
    }
}

__global__ void zero_gram()
{
    int i = blockIdx.x * 256 + threadIdx.x;
    if (i < B_*HEADS*32*32) g_gram[i] = 0.f;
}

// ---------------- 32x32 Gram per (b,h), N split 8 ways, atomic accumulate -----
__global__ __launch_bounds__(256) void gram_kernel(const float* __restrict__ q,
                                                   const float* __restrict__ kk)
{
    int split = blockIdx.x;              // 0..7
    int bh = blockIdx.y;                 // 0..23
    int b = bh / HEADS, h = bh % HEADS;
    __shared__ float qs[32][65], ks[32][65];
    const float* qb = q  + ((size_t)b*C_   + h*32)*HW_;
    const float* kb = kk + ((size_t)b*2*C_ + h*32)*HW_;
    int n0 = split * (HW_/8);
    int tid = threadIdx.x;
    int c = tid >> 3, d0 = (tid & 7) << 2;
    float acc[4] = {0.f, 0.f, 0.f, 0.f};
    for (int nt = 0; nt < HW_/8; nt += 64) {
        for (int l = tid; l < 2048; l += 256) {
            int cc = l >> 6, nn = l & 63;
            size_t off = (size_t)cc*HW_ + n0 + nt + nn;
            qs[cc][nn] = qb[off];
            ks[cc][nn] = kb[off];
        }
        __syncthreads();
        #pragma unroll 8
        for (int n = 0; n < 64; n++) {
            float qv = qs[c][n];
            #pragma unroll
            for (int j = 0; j < 4; j++) acc[j] += qv * ks[d0+j][n];
        }
        __syncthreads();
    }
    #pragma unroll
    for (int j = 0; j < 4; j++)
        atomicAdd(&g_gram[((size_t)bh*32 + c)*32 + d0 + j], acc[j]);
}

// ---------------- scale + softmax + fold with proj_w --> W_eff ---------------
// W_eff[b][co][h*32+d] = sum_c proj[co][h*32+c] * attn[b,h,c,d]
__global__ __launch_bounds__(256) void softfold(const float* __restrict__ temp,
                                                const float* __restrict__ proj)
{
    int bh = blockIdx.x;
    int b = bh / HEADS, h = bh % HEADS;
    __shared__ float attn[32][33];
    int tid = threadIdx.x;
    int wrp = tid >> 5, ln = tid & 31;
    float tmp = temp[h];
    for (int r = wrp; r < 32; r += 8) {
        float v = g_gram[((size_t)bh*32 + r)*32 + ln]
                * g_invq[b*C_ + h*32 + r] * g_invk[b*C_ + h*32 + ln] * tmp;
        float m = v;
        #pragma unroll
        for (int off = 16; off; off >>= 1) m = fmaxf(m, __shfl_xor_sync(0xffffffff, m, off));
        float e = expf(v - m);
        float s = e;
        #pragma unroll
        for (int off = 16; off; off >>= 1) s += __shfl_xor_sync(0xffffffff, s, off);
        attn[r][ln] = e / s;
    }
    __syncthreads();
    for (int l = tid; l < C_*32; l += 256) {
        int co = l >> 5, d = l & 31;
        float s = 0.f;
        #pragma unroll
        for (int cc = 0; cc < 32; cc++)
            s += proj[(size_t)co*C_ + h*32 + cc] * attn[cc][d];
        g_weff[((size_t)b*C_ + co)*C_ + h*32 + d] = s;
    }
}

// ---------------- launcher ----------------------------------------------------
extern "C" void kernel_launch(void* const* d_in, const int* in_sizes, int n_in,
                              void* d_out, int out_size)
{
    const float* x           = (const float*)d_in[0];
    const float* y           = (const float*)d_in[1];
    const float* q_w         = (const float*)d_in[2];
    const float* kv_w        = (const float*)d_in[3];
    const float* kvdw_w      = (const float*)d_in[4];
    const float* proj_w      = (const float*)d_in[5];
    const float* temperature = (const float*)d_in[6];

    float *p_kv, *p_kvd, *p_q, *p_invq, *p_invk, *p_weff;
    cudaGetSymbolAddress((void**)&p_kv,   g_kv);
    cudaGetSymbolAddress((void**)&p_kvd,  g_kvd);
    cudaGetSymbolAddress((void**)&p_q,    g_q);
    cudaGetSymbolAddress((void**)&p_invq, g_invq);
    cudaGetSymbolAddress((void**)&p_invk, g_invk);
    cudaGetSymbolAddress((void**)&p_weff, g_weff);

    // kv = kv_w (384x192) @ y   (1x1 conv as GEMM)
    gemm64<<<dim3(HW_/64, 384/64, B_), 256>>>(
        kv_w, 0, y, (size_t)C_*HW_, p_kv, (size_t)2*C_*HW_, C_);

    // depthwise 3x3 on kv -> [k | v]
    {
        size_t total = (size_t)B_*2*C_*HW_;
        dwconv3x3<<<(unsigned)((total + 255)/256), 256>>>(p_kv, kvdw_w, p_kvd);
    }

    // q = conv3x3(x, q_w)
    conv3x3<<<dim3(H_*(W_/64), C_/64, B_), 256>>>(x, q_w, p_q);

    // inverse L2 norms over HW per channel
    invnorm<<<B_*C_, 256>>>(p_q,   C_,   p_invq);
    invnorm<<<B_*C_, 256>>>(p_kvd, 2*C_, p_invk);

    // Gram(q,k) per (b,h), then softmax + fold proj -> W_eff
    zero_gram<<<(B_*HEADS*32*32 + 255)/256, 256>>>();
    gram_kernel<<<dim3(8, B_*HEADS), 256>>>(p_q, p_kvd);
    softfold<<<B_*HEADS, 256>>>(temperature, proj_w);

    // out = W_eff[b] (192x192) @ v[b]  (fuses attn@v and the 1x1 proj)
    gemm64<<<dim3(HW_/64, C_/64, B_), 256>>>(
        p_weff, (size_t)C_*C_, p_kvd + (size_t)C_*HW_, (size_t)2*C_*HW_,
        (float*)d_out, (size_t)C_*HW_, C_);
}

// round 7
// speedup vs baseline: 2.9711x; 2.9711x over previous
#include <cuda_runtime.h>
#include <cuda_fp16.h>
#include <math.h>
#include <stdint.h>

#define B_ 4
#define C_ 192
#define H_ 192
#define W_ 192
#define HW_ (H_*W_)
#define HEADS 6
#define PW 194
#define KTOT 192
#define NT 192

// ------------------ scratch ------------------
__device__ __align__(128) __half g_xh[(size_t)B_*PW*PW*C_], g_xl[(size_t)B_*PW*PW*C_];
__device__ __align__(128) __half g_yh[(size_t)B_*HW_*C_],   g_yl[(size_t)B_*HW_*C_];
__device__ __align__(128) __half g_vh[(size_t)B_*HW_*C_],   g_vl[(size_t)B_*HW_*C_];
__device__ __align__(128) __half g_kvwh[384*192], g_kvwl[384*192];
__device__ __align__(128) __half g_qwh[256*9*192], g_qwl[256*9*192];
__device__ __align__(128) __half g_wfh[B_*256*192], g_wfl[B_*256*192];
__device__ __align__(128) float  g_kv [(size_t)B_*2*C_*HW_];
__device__ __align__(128) float  g_kvd[(size_t)B_*2*C_*HW_];
__device__ __align__(128) float  g_q  [(size_t)B_*C_*HW_];
__device__ __align__(128) float  g_invq[B_*C_], g_invk[B_*C_];
__device__ __align__(128) float  g_gram[B_*HEADS*32*32];
__device__ __align__(128) float  g_weff[(size_t)B_*C_*C_];

// ------------------ PTX helpers (baseline features only: sm_80-class) --------
__device__ __forceinline__ uint32_t s2u(const void* p){
    uint32_t a;
    asm("{ .reg .u64 t; cvta.to.shared.u64 t, %1; cvt.u32.u64 %0, t; }":"=r"(a):"l"(p));
    return a;
}
#define SWZ(o) ((o) ^ (((o)>>3)&0x70))
__device__ __forceinline__ void cpa16(uint32_t d, const void* s){
    asm volatile("cp.async.cg.shared.global [%0], [%1], 16;"::"r"(d),"l"(s));
}
__device__ __forceinline__ void ldsm4(uint32_t* r, uint32_t a){
    asm volatile("ldmatrix.sync.aligned.m8n8.x4.shared.b16 {%0,%1,%2,%3}, [%4];"
        :"=r"(r[0]),"=r"(r[1]),"=r"(r[2]),"=r"(r[3]):"r"(a));
}
__device__ __forceinline__ void ldsm2(uint32_t* r, uint32_t a){
    asm volatile("ldmatrix.sync.aligned.m8n8.x2.shared.b16 {%0,%1}, [%2];"
        :"=r"(r[0]),"=r"(r[1]):"r"(a));
}
__device__ __forceinline__ void mma16816(float* c, const uint32_t* a, const uint32_t* b){
    asm volatile("mma.sync.aligned.m16n8k16.row.col.f32.f16.f16.f32 "
        "{%0,%1,%2,%3}, {%4,%5,%6,%7}, {%8,%9}, {%0,%1,%2,%3};"
        : "+f"(c[0]),"+f"(c[1]),"+f"(c[2]),"+f"(c[3])
        : "r"(a[0]),"r"(a[1]),"r"(a[2]),"r"(a[3]),"r"(b[0]),"r"(b[1]));
}

// ------------------ prepack kernels ------------------
__device__ __forceinline__ void split_h(float v, __half& h, __half& l){
    h = __float2half_rn(v);
    l = __float2half_rn(v - __half2float(h));
}

// fp32 [C][HW] -> fp16 hi/lo [HW][C] (pixel-major)
__global__ void t32(const float* __restrict__ src, size_t sBatch,
                    __half* __restrict__ dh, __half* __restrict__ dl)
{
    __shared__ float t[32][33];
    int p0 = blockIdx.x*32, c0 = blockIdx.y*32, b = blockIdx.z;
    const float* s = src + (size_t)b*sBatch;
    int tx = threadIdx.x, ty = threadIdx.y;
    #pragma unroll
    for (int j=0;j<4;j++)
        t[ty+8*j][tx] = s[(size_t)(c0+ty+8*j)*HW_ + p0+tx];
    __syncthreads();
    #pragma unroll
    for (int j=0;j<4;j++){
        __half hh,ll; split_h(t[tx][ty+8*j], hh, ll);
        size_t o = ((size_t)b*HW_ + p0+ty+8*j)*C_ + c0+tx;
        dh[o]=hh; dl[o]=ll;
    }
}

// fp32 x [C][HW] -> padded fp16 hi/lo [194][194][C]
__global__ void t32pad(const float* __restrict__ src,
                       __half* __restrict__ dh, __half* __restrict__ dl)
{
    __shared__ float t[32][33];
    int p0 = blockIdx.x*32, c0 = blockIdx.y*32, b = blockIdx.z;
    const float* s = src + (size_t)b*C_*HW_;
    int tx = threadIdx.x, ty = threadIdx.y;
    #pragma unroll
    for (int j=0;j<4;j++)
        t[ty+8*j][tx] = s[(size_t)(c0+ty+8*j)*HW_ + p0+tx];
    __syncthreads();
    #pragma unroll
    for (int j=0;j<4;j++){
        __half hh,ll; split_h(t[tx][ty+8*j], hh, ll);
        int p = p0+ty+8*j, yy = p/W_, xx = p%W_;
        size_t o = ((size_t)b*PW*PW + (size_t)(yy+1)*PW + (xx+1))*C_ + c0+tx;
        dh[o]=hh; dl[o]=ll;
    }
}

__global__ void zb(__half* __restrict__ dh, __half* __restrict__ dl)
{
    int i = blockIdx.x*256 + threadIdx.x;
    const int per_b = 772*C_;
    if (i >= B_*per_b) return;
    int b = i/per_b, rem = i%per_b, ridx = rem/C_, c = rem%C_;
    int yy, xx;
    if (ridx < 194)      { yy=0;   xx=ridx; }
    else if (ridx < 388) { yy=193; xx=ridx-194; }
    else if (ridx < 580) { yy=ridx-388+1; xx=0; }
    else                 { yy=ridx-580+1; xx=193; }
    size_t o = ((size_t)b*PW*PW + (size_t)yy*PW + xx)*C_ + c;
    dh[o] = __float2half_rn(0.f); dl[o] = __float2half_rn(0.f);
}

__global__ void pack_kvw(const float* __restrict__ w,
                         __half* __restrict__ h, __half* __restrict__ l)
{
    int i = blockIdx.x*256 + threadIdx.x;
    if (i >= 384*192) return;
    __half hh,ll; split_h(w[i], hh, ll); h[i]=hh; l[i]=ll;
}

// q_w [192][192][3][3] -> [256][9][192], oc>=192 zero
__global__ void pack_qw(const float* __restrict__ w,
                        __half* __restrict__ h, __half* __restrict__ l)
{
    int i = blockIdx.x*256 + threadIdx.x;
    if (i >= 256*9*192) return;
    int oc = i/(9*192), rem = i%(9*192), t = rem/192, ic = rem%192;
    float v = (oc < 192) ? w[((size_t)(oc*192+ic))*9 + t] : 0.f;
    __half hh,ll; split_h(v, hh, ll); h[i]=hh; l[i]=ll;
}

// g_weff fp32 [b][192][192] -> hi/lo [b][256][192], rows>=192 zero
__global__ void pack_weff(__half* __restrict__ h, __half* __restrict__ l)
{
    int i = blockIdx.x*256 + threadIdx.x;
    if (i >= B_*256*192) return;
    int b = i/(256*192), rem = i%(256*192), r = rem/192, c = rem%192;
    float v = (r < 192) ? g_weff[((size_t)b*C_ + r)*C_ + c] : 0.f;
    __half hh,ll; split_h(v, hh, ll); h[i]=hh; l[i]=ll;
}

// ------------------ warp-MMA GEMM / conv (mma.sync, double-buffered) ---------
// Y[b](128 x 192) = sum_{tap,K} A[b](row-major, TAPS*192 per row, hi/lo)
//                             * B[b](pixel-major [row][192], hi/lo)^T
// 256 thr = 8 warps (2m x 4n), warp tile 64x48, k-chunk 64, 2-stage cp.async.
// SMEM per stage: A_h 16K @0, A_l 16K @16384, B_h 24K @32768, B_l 24K @57344.
template<int TAPS>
__global__ __launch_bounds__(256,1) void hgemm(
    const __half* __restrict__ Ah, const __half* __restrict__ Al, size_t aBatch,
    const __half* __restrict__ Bh, const __half* __restrict__ Bl, size_t bBatch,
    size_t bRowStride, float* __restrict__ out, size_t oBatch, int M_real)
{
    extern __shared__ char smem[];
    uint32_t sb = s2u(smem);
    const int NC = 3*TAPS;
    int tid = threadIdx.x, lane = tid&31, wid = tid>>5;
    int wm = wid&1, wn = wid>>1;
    int bx = blockIdx.x, b = blockIdx.y, m0 = blockIdx.z*128;
    const __half* Ahb = Ah + (size_t)b*aBatch;
    const __half* Alb = Al + (size_t)b*aBatch;
    const __half* Bhb = Bh + (size_t)b*bBatch + (size_t)bx*bRowStride;
    const __half* Blb = Bl + (size_t)b*bBatch + (size_t)bx*bRowStride;

    auto load = [&](int it){
        uint32_t base = sb + (uint32_t)(it&1)*81920u;
        int tap = (TAPS==9)? it/3 : 0;
        int kc  = (TAPS==9)? it%3 : it;
        size_t tapOff = (TAPS==9)? (size_t)((tap/3)*PW + (tap%3))*C_ : 0;
        #pragma unroll
        for (int i=0;i<4;i++){                    // A: 128 rows x 8 x 16B
            int idx = tid + i*256; int r = idx>>3, j = idx&7;
            size_t ge = (size_t)(m0+r)*((size_t)TAPS*KTOT) + (size_t)tap*KTOT + kc*64;
            uint32_t off = SWZ((uint32_t)(r*128 + j*16));
            cpa16(base + 0u     + off, (const char*)(Ahb+ge) + j*16);
            cpa16(base + 16384u + off, (const char*)(Alb+ge) + j*16);
        }
        #pragma unroll
        for (int i=0;i<6;i++){                    // B: 192 rows x 8 x 16B
            int idx = tid + i*256; int r = idx>>3, j = idx&7;
            size_t ge = tapOff + (size_t)r*KTOT + kc*64;
            uint32_t off = SWZ((uint32_t)(r*128 + j*16));
            cpa16(base + 32768u + off, (const char*)(Bhb+ge) + j*16);
            cpa16(base + 57344u + off, (const char*)(Blb+ge) + j*16);
        }
        asm volatile("cp.async.commit_group;":::"memory");
    };

    float acc[4][6][4] = {};

    load(0);
    #pragma unroll 1
    for (int it=0; it<NC; it++){
        if (it+1 < NC){
            load(it+1);
            asm volatile("cp.async.wait_group 1;":::"memory");
        } else {
            asm volatile("cp.async.wait_group 0;":::"memory");
        }
        __syncthreads();
        uint32_t base = sb + (uint32_t)(it&1)*81920u;
        #pragma unroll
        for (int kk=0;kk<4;kk++){
            uint32_t ah[4][4], al[4][4], bh[6][2], bl[6][2];
            #pragma unroll
            for (int mt=0;mt<4;mt++){
                int row = wm*64 + mt*16 + (lane&15);
                uint32_t off = SWZ((uint32_t)(row*128 + (2*kk + (lane>>4))*16));
                ldsm4(ah[mt], base + 0u     + off);
                ldsm4(al[mt], base + 16384u + off);
            }
            #pragma unroll
            for (int nt=0;nt<6;nt++){
                int rn = wn*48 + nt*8 + (lane&7);
                uint32_t off = SWZ((uint32_t)(rn*128 + (2*kk + ((lane>>3)&1))*16));
                ldsm2(bh[nt], base + 32768u + off);
                ldsm2(bl[nt], base + 57344u + off);
            }
            #pragma unroll
            for (int mt=0;mt<4;mt++)
                #pragma unroll
                for (int nt=0;nt<6;nt++){
                    mma16816(acc[mt][nt], ah[mt], bh[nt]);
                    mma16816(acc[mt][nt], ah[mt], bl[nt]);
                    mma16816(acc[mt][nt], al[mt], bh[nt]);
                }
        }
        __syncthreads();
    }

    // epilogue: c0,c1 at (row, col..col+1), c2,c3 at (row+8, ...)
    #pragma unroll
    for (int mt=0;mt<4;mt++){
        int row = m0 + wm*64 + mt*16 + (lane>>2);
        #pragma unroll
        for (int nt=0;nt<6;nt++){
            int col = bx*NT + wn*48 + nt*8 + (lane&3)*2;
            if (row < M_real){
                float2* p = (float2*)(out + (size_t)b*oBatch + (size_t)row*HW_ + col);
                *p = make_float2(acc[mt][nt][0], acc[mt][nt][1]);
            }
            if (row+8 < M_real){
                float2* p = (float2*)(out + (size_t)b*oBatch + (size_t)(row+8)*HW_ + col);
                *p = make_float2(acc[mt][nt][2], acc[mt][nt][3]);
            }
        }
    }
}

// ------------------ fp32 tail kernels ------------------
__global__ void dwconv3x3(const float* __restrict__ in, const float* __restrict__ w,
                          float* __restrict__ out)
{
    size_t idx = (size_t)blockIdx.x * 256 + threadIdx.x;
    const size_t total = (size_t)B_*2*C_*HW_;
    if (idx >= total) return;
    int n  = (int)(idx % HW_);
    int ch = (int)((idx / HW_) % (2*C_));
    int px = n % W_, py = n / W_;
    const float* base = in + (idx - n);
    float s = 0.f;
    #pragma unroll
    for (int ky = 0; ky < 3; ky++) {
        int gy = py + ky - 1;
        if ((unsigned)gy >= (unsigned)H_) continue;
        #pragma unroll
        for (int kx = 0; kx < 3; kx++) {
            int gx = px + kx - 1;
            if ((unsigned)gx >= (unsigned)W_) continue;
            s += w[ch*9 + ky*3 + kx] * base[(size_t)gy*W_ + gx];
        }
    }
    out[idx] = s;
}

__global__ __launch_bounds__(256) void invnorm(const float* __restrict__ src,
                                               int chanPerB, float* __restrict__ dst)
{
    int bc = blockIdx.x;
    int b = bc / C_, c = bc % C_;
    const float4* p = reinterpret_cast<const float4*>(src + ((size_t)b*chanPerB + c)*HW_);
    float ss = 0.f;
    for (int i = threadIdx.x; i < HW_/4; i += 256) {
        float4 v = p[i];
        ss += v.x*v.x + v.y*v.y + v.z*v.z + v.w*v.w;
    }
    #pragma unroll
    for (int off = 16; off; off >>= 1) ss += __shfl_xor_sync(0xffffffff, ss, off);
    __shared__ float red[8];
    if ((threadIdx.x & 31) == 0) red[threadIdx.x >> 5] = ss;
    __syncthreads();
    if (threadIdx.x == 0) {
        float t = 0.f;
        #pragma unroll
        for (int i = 0; i < 8; i++) t += red[i];
        dst[bc] = 1.f / fmaxf(sqrtf(t), 1e-12f);
    }
}

__global__ void zero_gram()
{
    int i = blockIdx.x * 256 + threadIdx.x;
    if (i < B_*HEADS*32*32) g_gram[i] = 0.f;
}

__global__ __launch_bounds__(256) void gram_kernel(const float* __restrict__ q,
                                                   const float* __restrict__ kk)
{
    int split = blockIdx.x;
    int bh = blockIdx.y;
    int b = bh / HEADS, h = bh % HEADS;
    __shared__ float qs[32][65], ks[32][65];
    const float* qb = q  + ((size_t)b*C_   + h*32)*HW_;
    const float* kb = kk + ((size_t)b*2*C_ + h*32)*HW_;
    int n0 = split * (HW_/8);
    int tid = threadIdx.x;
    int c = tid >> 3, d0 = (tid & 7) << 2;
    float acc[4] = {0.f, 0.f, 0.f, 0.f};
    for (int nt = 0; nt < HW_/8; nt += 64) {
        for (int l = tid; l < 2048; l += 256) {
            int cc = l >> 6, nn = l & 63;
            size_t off = (size_t)cc*HW_ + n0 + nt + nn;
            qs[cc][nn] = qb[off];
            ks[cc][nn] = kb[off];
        }
        __syncthreads();
        #pragma unroll 8
        for (int n = 0; n < 64; n++) {
            float qv = qs[c][n];
            #pragma unroll
            for (int j = 0; j < 4; j++) acc[j] += qv * ks[d0+j][n];
        }
        __syncthreads();
    }
    #pragma unroll
    for (int j = 0; j < 4; j++)
        atomicAdd(&g_gram[((size_t)bh*32 + c)*32 + d0 + j], acc[j]);
}

__global__ __launch_bounds__(256) void softfold(const float* __restrict__ temp,
                                                const float* __restrict__ proj)
{
    int bh = blockIdx.x;
    int b = bh / HEADS, h = bh % HEADS;
    __shared__ float attn[32][33];
    int tid = threadIdx.x;
    int wrp = tid >> 5, ln = tid & 31;
    float tmp = temp[h];
    for (int r = wrp; r < 32; r += 8) {
        float v = g_gram[((size_t)bh*32 + r)*32 + ln]
                * g_invq[b*C_ + h*32 + r] * g_invk[b*C_ + h*32 + ln] * tmp;
        float m = v;
        #pragma unroll
        for (int off = 16; off; off >>= 1) m = fmaxf(m, __shfl_xor_sync(0xffffffff, m, off));
        float e = expf(v - m);
        float s = e;
        #pragma unroll
        for (int off = 16; off; off >>= 1) s += __shfl_xor_sync(0xffffffff, s, off);
        attn[r][ln] = e / s;
    }
    __syncthreads();
    for (int l = tid; l < C_*32; l += 256) {
        int co = l >> 5, d = l & 31;
        float s = 0.f;
        #pragma unroll
        for (int cc = 0; cc < 32; cc++)
            s += proj[(size_t)co*C_ + h*32 + cc] * attn[cc][d];
        g_weff[((size_t)b*C_ + co)*C_ + h*32 + d] = s;
    }
}

// ------------------ launcher ------------------
extern "C" void kernel_launch(void* const* d_in, const int* in_sizes, int n_in,
                              void* d_out, int out_size)
{
    const float* x           = (const float*)d_in[0];
    const float* y           = (const float*)d_in[1];
    const float* q_w         = (const float*)d_in[2];
    const float* kv_w        = (const float*)d_in[3];
    const float* kvdw_w      = (const float*)d_in[4];
    const float* proj_w      = (const float*)d_in[5];
    const float* temperature = (const float*)d_in[6];

    float *p_kv, *p_kvd, *p_q, *p_invq, *p_invk;
    __half *p_xh,*p_xl,*p_yh,*p_yl,*p_vh,*p_vl,*p_kvwh,*p_kvwl,*p_qwh,*p_qwl,*p_wfh,*p_wfl;
    cudaGetSymbolAddress((void**)&p_kv, g_kv);   cudaGetSymbolAddress((void**)&p_kvd, g_kvd);
    cudaGetSymbolAddress((void**)&p_q, g_q);
    cudaGetSymbolAddress((void**)&p_invq, g_invq); cudaGetSymbolAddress((void**)&p_invk, g_invk);
    cudaGetSymbolAddress((void**)&p_xh, g_xh);   cudaGetSymbolAddress((void**)&p_xl, g_xl);
    cudaGetSymbolAddress((void**)&p_yh, g_yh);   cudaGetSymbolAddress((void**)&p_yl, g_yl);
    cudaGetSymbolAddress((void**)&p_vh, g_vh);   cudaGetSymbolAddress((void**)&p_vl, g_vl);
    cudaGetSymbolAddress((void**)&p_kvwh, g_kvwh); cudaGetSymbolAddress((void**)&p_kvwl, g_kvwl);
    cudaGetSymbolAddress((void**)&p_qwh, g_qwh); cudaGetSymbolAddress((void**)&p_qwl, g_qwl);
    cudaGetSymbolAddress((void**)&p_wfh, g_wfh); cudaGetSymbolAddress((void**)&p_wfl, g_wfl);

    const int SMEM = 163840;   // 2 stages x 80KB
    cudaFuncSetAttribute(hgemm<1>, cudaFuncAttributeMaxDynamicSharedMemorySize, SMEM);
    cudaFuncSetAttribute(hgemm<9>, cudaFuncAttributeMaxDynamicSharedMemorySize, SMEM);

    dim3 tb(32,8);
    // prepack
    pack_kvw<<<(384*192+255)/256, 256>>>(kv_w, p_kvwh, p_kvwl);
    pack_qw <<<(256*9*192+255)/256, 256>>>(q_w, p_qwh, p_qwl);
    t32pad<<<dim3(HW_/32, C_/32, B_), tb>>>(x, p_xh, p_xl);
    zb<<<(B_*772*C_+255)/256, 256>>>(p_xh, p_xl);
    t32<<<dim3(HW_/32, C_/32, B_), tb>>>(y, (size_t)C_*HW_, p_yh, p_yl);

    // kv = kv_w(384x192) @ y  -> g_kv fp32
    hgemm<1><<<dim3(HW_/NT, B_, 3), 256, SMEM>>>(
        p_kvwh, p_kvwl, 0, p_yh, p_yl, (size_t)HW_*C_, (size_t)NT*C_,
        p_kv, (size_t)2*C_*HW_, 384);

    // depthwise 3x3 -> g_kvd = [k|v]
    {
        size_t total = (size_t)B_*2*C_*HW_;
        dwconv3x3<<<(unsigned)((total+255)/256), 256>>>(p_kv, kvdw_w, p_kvd);
    }

    // q = conv3x3(x) via 9 shifted GEMMs
    hgemm<9><<<dim3(H_, B_, 2), 256, SMEM>>>(
        p_qwh, p_qwl, 0, p_xh, p_xl, (size_t)PW*PW*C_, (size_t)PW*C_,
        p_q, (size_t)C_*HW_, C_);

    // v -> pixel-major fp16 hi/lo
    t32<<<dim3(HW_/32, C_/32, B_), tb>>>(p_kvd + (size_t)C_*HW_, (size_t)2*C_*HW_, p_vh, p_vl);

    invnorm<<<B_*C_, 256>>>(p_q,   C_,   p_invq);
    invnorm<<<B_*C_, 256>>>(p_kvd, 2*C_, p_invk);

    zero_gram<<<(B_*HEADS*32*32+255)/256, 256>>>();
    gram_kernel<<<dim3(8, B_*HEADS), 256>>>(p_q, p_kvd);
    softfold<<<B_*HEADS, 256>>>(temperature, proj_w);
    pack_weff<<<(B_*256*192+255)/256, 256>>>(p_wfh, p_wfl);

    // out = W_eff[b](192x192) @ v[b]
    hgemm<1><<<dim3(HW_/NT, B_, 2), 256, SMEM>>>(
        p_wfh, p_wfl, (size_t)256*192, p_vh, p_vl, (size_t)HW_*C_, (size_t)NT*C_,
        (float*)d_out, (size_t)C_*HW_, C_);
}

// round 8
// speedup vs baseline: 3.4308x; 1.1547x over previous
#include <cuda_runtime.h>
#include <cuda_fp16.h>
#include <math.h>
#include <stdint.h>

#define B_ 4
#define C_ 192
#define H_ 192
#define W_ 192
#define HW_ (H_*W_)
#define HEADS 6
#define PW 194
#define KTOT 192
#define NT 192

// ------------------ scratch ------------------
__device__ __align__(128) __half g_xh[(size_t)B_*PW*PW*C_], g_xl[(size_t)B_*PW*PW*C_];
__device__ __align__(128) __half g_yh[(size_t)B_*HW_*C_],   g_yl[(size_t)B_*HW_*C_];
__device__ __align__(128) __half g_vh[(size_t)B_*HW_*C_],   g_vl[(size_t)B_*HW_*C_];
__device__ __align__(128) __half g_kvwh[384*192], g_kvwl[384*192];
__device__ __align__(128) __half g_qwh[256*9*192], g_qwl[256*9*192];
__device__ __align__(128) __half g_wfh[B_*256*192], g_wfl[B_*256*192];
__device__ __align__(128) float  g_kv [(size_t)B_*2*C_*HW_];
__device__ __align__(128) float  g_kvd[(size_t)B_*2*C_*HW_];
__device__ __align__(128) float  g_q  [(size_t)B_*C_*HW_];
__device__ __align__(128) float  g_invq[B_*C_], g_invk[B_*C_];
__device__ __align__(128) float  g_gram[B_*HEADS*32*32];
__device__ __align__(128) float  g_weff[(size_t)B_*C_*C_];

// ------------------ PTX helpers (baseline features only) ------------------
__device__ __forceinline__ uint32_t s2u(const void* p){
    uint32_t a;
    asm("{ .reg .u64 t; cvta.to.shared.u64 t, %1; cvt.u32.u64 %0, t; }":"=r"(a):"l"(p));
    return a;
}
#define SWZ(o) ((o) ^ (((o)>>3)&0x70))
__device__ __forceinline__ void cpa16(uint32_t d, const void* s){
    asm volatile("cp.async.cg.shared.global [%0], [%1], 16;"::"r"(d),"l"(s));
}
__device__ __forceinline__ void ldsm4(uint32_t* r, uint32_t a){
    asm volatile("ldmatrix.sync.aligned.m8n8.x4.shared.b16 {%0,%1,%2,%3}, [%4];"
        :"=r"(r[0]),"=r"(r[1]),"=r"(r[2]),"=r"(r[3]):"r"(a));
}
__device__ __forceinline__ void ldsm2(uint32_t* r, uint32_t a){
    asm volatile("ldmatrix.sync.aligned.m8n8.x2.shared.b16 {%0,%1}, [%2];"
        :"=r"(r[0]),"=r"(r[1]):"r"(a));
}
__device__ __forceinline__ void mma16816(float* c, const uint32_t* a, const uint32_t* b){
    asm volatile("mma.sync.aligned.m16n8k16.row.col.f32.f16.f16.f32 "
        "{%0,%1,%2,%3}, {%4,%5,%6,%7}, {%8,%9}, {%0,%1,%2,%3};"
        : "+f"(c[0]),"+f"(c[1]),"+f"(c[2]),"+f"(c[3])
        : "r"(a[0]),"r"(a[1]),"r"(a[2]),"r"(a[3]),"r"(b[0]),"r"(b[1]));
}

// ------------------ prepack kernels ------------------
__device__ __forceinline__ void split_h(float v, __half& h, __half& l){
    h = __float2half_rn(v);
    l = __float2half_rn(v - __half2float(h));
}

// fp32 [C][HW] -> fp16 hi/lo [HW][C] (pixel-major)
__global__ void t32(const float* __restrict__ src, size_t sBatch,
                    __half* __restrict__ dh, __half* __restrict__ dl)
{
    __shared__ float t[32][33];
    int p0 = blockIdx.x*32, c0 = blockIdx.y*32, b = blockIdx.z;
    const float* s = src + (size_t)b*sBatch;
    int tx = threadIdx.x, ty = threadIdx.y;
    #pragma unroll
    for (int j=0;j<4;j++)
        t[ty+8*j][tx] = s[(size_t)(c0+ty+8*j)*HW_ + p0+tx];
    __syncthreads();
    #pragma unroll
    for (int j=0;j<4;j++){
        __half hh,ll; split_h(t[tx][ty+8*j], hh, ll);
        size_t o = ((size_t)b*HW_ + p0+ty+8*j)*C_ + c0+tx;
        dh[o]=hh; dl[o]=ll;
    }
}

// fp32 x [C][HW] -> padded fp16 hi/lo [194][194][C]
__global__ void t32pad(const float* __restrict__ src,
                       __half* __restrict__ dh, __half* __restrict__ dl)
{
    __shared__ float t[32][33];
    int p0 = blockIdx.x*32, c0 = blockIdx.y*32, b = blockIdx.z;
    const float* s = src + (size_t)b*C_*HW_;
    int tx = threadIdx.x, ty = threadIdx.y;
    #pragma unroll
    for (int j=0;j<4;j++)
        t[ty+8*j][tx] = s[(size_t)(c0+ty+8*j)*HW_ + p0+tx];
    __syncthreads();
    #pragma unroll
    for (int j=0;j<4;j++){
        __half hh,ll; split_h(t[tx][ty+8*j], hh, ll);
        int p = p0+ty+8*j, yy = p/W_, xx = p%W_;
        size_t o = ((size_t)b*PW*PW + (size_t)(yy+1)*PW + (xx+1))*C_ + c0+tx;
        dh[o]=hh; dl[o]=ll;
    }
}

__global__ void zb(__half* __restrict__ dh, __half* __restrict__ dl)
{
    int i = blockIdx.x*256 + threadIdx.x;
    const int per_b = 772*C_;
    if (i >= B_*per_b) return;
    int b = i/per_b, rem = i%per_b, ridx = rem/C_, c = rem%C_;
    int yy, xx;
    if (ridx < 194)      { yy=0;   xx=ridx; }
    else if (ridx < 388) { yy=193; xx=ridx-194; }
    else if (ridx < 580) { yy=ridx-388+1; xx=0; }
    else                 { yy=ridx-580+1; xx=193; }
    size_t o = ((size_t)b*PW*PW + (size_t)yy*PW + xx)*C_ + c;
    dh[o] = __float2half_rn(0.f); dl[o] = __float2half_rn(0.f);
}

__global__ void pack_kvw(const float* __restrict__ w,
                         __half* __restrict__ h, __half* __restrict__ l)
{
    int i = blockIdx.x*256 + threadIdx.x;
    if (i >= 384*192) return;
    __half hh,ll; split_h(w[i], hh, ll); h[i]=hh; l[i]=ll;
}

// q_w [192][192][3][3] -> [256][9][192], oc>=192 zero
__global__ void pack_qw(const float* __restrict__ w,
                        __half* __restrict__ h, __half* __restrict__ l)
{
    int i = blockIdx.x*256 + threadIdx.x;
    if (i >= 256*9*192) return;
    int oc = i/(9*192), rem = i%(9*192), t = rem/192, ic = rem%192;
    float v = (oc < 192) ? w[((size_t)(oc*192+ic))*9 + t] : 0.f;
    __half hh,ll; split_h(v, hh, ll); h[i]=hh; l[i]=ll;
}

// g_weff fp32 [b][192][192] -> hi/lo [b][256][192], rows>=192 zero
__global__ void pack_weff(__half* __restrict__ h, __half* __restrict__ l)
{
    int i = blockIdx.x*256 + threadIdx.x;
    if (i >= B_*256*192) return;
    int b = i/(256*192), rem = i%(256*192), r = rem/192, c = rem%192;
    float v = (r < 192) ? g_weff[((size_t)b*C_ + r)*C_ + c] : 0.f;
    __half hh,ll; split_h(v, hh, ll); h[i]=hh; l[i]=ll;
}

// ------------------ warp-MMA GEMM / conv (mma.sync, double-buffered) ---------
// Block tile BM x 192. 256 thr = 8 warps (2m x 4n).
// BM=128: warp tile 64x48 (mt=4); BM=64: warp tile 32x48 (mt=2).
// SMEM per stage: A_h (BM*128) @0, A_l @ASZ, B_h 24K @2*ASZ, B_l @2*ASZ+24576.
template<int TAPS, int BM>
__global__ __launch_bounds__(256,1) void hgemm(
    const __half* __restrict__ Ah, const __half* __restrict__ Al, size_t aBatch,
    const __half* __restrict__ Bh, const __half* __restrict__ Bl, size_t bBatch,
    size_t bRowStride, float* __restrict__ out, size_t oBatch,
    int m0base, int M_real)
{
    constexpr int MT = BM/32;                 // m-frags per warp
    constexpr uint32_t ASZ = (uint32_t)BM*128u;
    constexpr uint32_t STG = 2u*ASZ + 49152u; // stage size
    extern __shared__ char smem[];
    uint32_t sb = s2u(smem);
    const int NC = 3*TAPS;
    int tid = threadIdx.x, lane = tid&31, wid = tid>>5;
    int wm = wid&1, wn = wid>>1;
    int bx = blockIdx.x, b = blockIdx.y;
    int m0 = m0base + blockIdx.z*BM;
    const __half* Ahb = Ah + (size_t)b*aBatch;
    const __half* Alb = Al + (size_t)b*aBatch;
    const __half* Bhb = Bh + (size_t)b*bBatch + (size_t)bx*bRowStride;
    const __half* Blb = Bl + (size_t)b*bBatch + (size_t)bx*bRowStride;

    auto load = [&](int it){
        uint32_t base = sb + (uint32_t)(it&1)*STG;
        int tap = (TAPS==9)? it/3 : 0;
        int kc  = (TAPS==9)? it%3 : it;
        size_t tapOff = (TAPS==9)? (size_t)((tap/3)*PW + (tap%3))*C_ : 0;
        #pragma unroll
        for (int i=0;i<BM/32;i++){               // A: BM rows x 8 x 16B
            int idx = tid + i*256; int r = idx>>3, j = idx&7;
            size_t ge = (size_t)(m0+r)*((size_t)TAPS*KTOT) + (size_t)tap*KTOT + kc*64;
            uint32_t off = SWZ((uint32_t)(r*128 + j*16));
            cpa16(base + 0u  + off, (const char*)(Ahb+ge) + j*16);
            cpa16(base + ASZ + off, (const char*)(Alb+ge) + j*16);
        }
        #pragma unroll
        for (int i=0;i<6;i++){                   // B: 192 rows x 8 x 16B
            int idx = tid + i*256; int r = idx>>3, j = idx&7;
            size_t ge = tapOff + (size_t)r*KTOT + kc*64;
            uint32_t off = SWZ((uint32_t)(r*128 + j*16));
            cpa16(base + 2u*ASZ          + off, (const char*)(Bhb+ge) + j*16);
            cpa16(base + 2u*ASZ + 24576u + off, (const char*)(Blb+ge) + j*16);
        }
        asm volatile("cp.async.commit_group;":::"memory");
    };

    float acc[MT][6][4] = {};

    load(0);
    #pragma unroll 1
    for (int it=0; it<NC; it++){
        if (it+1 < NC){
            load(it+1);
            asm volatile("cp.async.wait_group 1;":::"memory");
        } else {
            asm volatile("cp.async.wait_group 0;":::"memory");
        }
        __syncthreads();
        uint32_t base = sb + (uint32_t)(it&1)*STG;
        #pragma unroll
        for (int kk=0;kk<4;kk++){
            uint32_t ah[MT][4], al[MT][4], bh[6][2], bl[6][2];
            #pragma unroll
            for (int mt=0;mt<MT;mt++){
                int row = wm*(MT*16) + mt*16 + (lane&15);
                uint32_t off = SWZ((uint32_t)(row*128 + (2*kk + (lane>>4))*16));
                ldsm4(ah[mt], base + 0u  + off);
                ldsm4(al[mt], base + ASZ + off);
            }
            #pragma unroll
            for (int nt=0;nt<6;nt++){
                int rn = wn*48 + nt*8 + (lane&7);
                uint32_t off = SWZ((uint32_t)(rn*128 + (2*kk + ((lane>>3)&1))*16));
                ldsm2(bh[nt], base + 2u*ASZ          + off);
                ldsm2(bl[nt], base + 2u*ASZ + 24576u + off);
            }
            #pragma unroll
            for (int mt=0;mt<MT;mt++)
                #pragma unroll
                for (int nt=0;nt<6;nt++){
                    mma16816(acc[mt][nt], ah[mt], bh[nt]);
                    mma16816(acc[mt][nt], ah[mt], bl[nt]);
                    mma16816(acc[mt][nt], al[mt], bh[nt]);
                }
        }
        __syncthreads();
    }

    #pragma unroll
    for (int mt=0;mt<MT;mt++){
        int row = m0 + wm*(MT*16) + mt*16 + (lane>>2);
        #pragma unroll
        for (int nt=0;nt<6;nt++){
            int col = bx*NT + wn*48 + nt*8 + (lane&3)*2;
            if (row < M_real){
                float2* p = (float2*)(out + (size_t)b*oBatch + (size_t)row*HW_ + col);
                *p = make_float2(acc[mt][nt][0], acc[mt][nt][1]);
            }
            if (row+8 < M_real){
                float2* p = (float2*)(out + (size_t)b*oBatch + (size_t)(row+8)*HW_ + col);
                *p = make_float2(acc[mt][nt][2], acc[mt][nt][3]);
            }
        }
    }
}

// ------------------ depthwise 3x3, smem-tiled (each input read once) ----------
__global__ __launch_bounds__(256) void dwconv_t(const float* __restrict__ in,
                                                const float* __restrict__ w,
                                                float* __restrict__ out)
{
    __shared__ float s[34][196];
    int y0 = blockIdx.x*32;
    int ch = blockIdx.y;
    int b  = blockIdx.z;
    int tid = threadIdx.x;
    const float* src = in + ((size_t)b*2*C_ + ch)*HW_;
    for (int l = tid; l < 34*194; l += 256){
        int r = l/194, c = l%194;
        int gy = y0 + r - 1, gx = c - 1;
        float v = 0.f;
        if ((unsigned)gy < (unsigned)H_ && (unsigned)gx < (unsigned)W_)
            v = src[(size_t)gy*W_ + gx];
        s[r][c] = v;
    }
    float w0=w[ch*9+0], w1=w[ch*9+1], w2=w[ch*9+2],
          w3=w[ch*9+3], w4=w[ch*9+4], w5=w[ch*9+5],
          w6=w[ch*9+6], w7=w[ch*9+7], w8=w[ch*9+8];
    __syncthreads();
    float* dst = out + ((size_t)b*2*C_ + ch)*HW_ + (size_t)y0*W_;
    for (int l = tid; l < 32*192; l += 256){
        int r = l/192, c = l%192;
        float acc = w0*s[r  ][c] + w1*s[r  ][c+1] + w2*s[r  ][c+2]
                  + w3*s[r+1][c] + w4*s[r+1][c+1] + w5*s[r+1][c+2]
                  + w6*s[r+2][c] + w7*s[r+2][c+1] + w8*s[r+2][c+2];
        dst[(size_t)r*W_ + c] = acc;
    }
}

// ------------------ fp32 tail kernels ------------------
__global__ __launch_bounds__(256) void invnorm(const float* __restrict__ src,
                                               int chanPerB, float* __restrict__ dst)
{
    int bc = blockIdx.x;
    int b = bc / C_, c = bc % C_;
    const float4* p = reinterpret_cast<const float4*>(src + ((size_t)b*chanPerB + c)*HW_);
    float ss = 0.f;
    for (int i = threadIdx.x; i < HW_/4; i += 256) {
        float4 v = p[i];
        ss += v.x*v.x + v.y*v.y + v.z*v.z + v.w*v.w;
    }
    #pragma unroll
    for (int off = 16; off; off >>= 1) ss += __shfl_xor_sync(0xffffffff, ss, off);
    __shared__ float red[8];
    if ((threadIdx.x & 31) == 0) red[threadIdx.x >> 5] = ss;
    __syncthreads();
    if (threadIdx.x == 0) {
        float t = 0.f;
        #pragma unroll
        for (int i = 0; i < 8; i++) t += red[i];
        dst[bc] = 1.f / fmaxf(sqrtf(t), 1e-12f);
    }
}

__global__ void zero_gram()
{
    int i = blockIdx.x * 256 + threadIdx.x;
    if (i < B_*HEADS*32*32) g_gram[i] = 0.f;
}

__global__ __launch_bounds__(256) void gram_kernel(const float* __restrict__ q,
                                                   const float* __restrict__ kk)
{
    int split = blockIdx.x;
    int bh = blockIdx.y;
    int b = bh / HEADS, h = bh % HEADS;
    __shared__ float qs[32][65], ks[32][65];
    const float* qb = q  + ((size_t)b*C_   + h*32)*HW_;
    const float* kb = kk + ((size_t)b*2*C_ + h*32)*HW_;
    int n0 = split * (HW_/8);
    int tid = threadIdx.x;
    int c = tid >> 3, d0 = (tid & 7) << 2;
    float acc[4] = {0.f, 0.f, 0.f, 0.f};
    for (int nt = 0; nt < HW_/8; nt += 64) {
        for (int l = tid; l < 2048; l += 256) {
            int cc = l >> 6, nn = l & 63;
            size_t off = (size_t)cc*HW_ + n0 + nt + nn;
            qs[cc][nn] = qb[off];
            ks[cc][nn] = kb[off];
        }
        __syncthreads();
        #pragma unroll 8
        for (int n = 0; n < 64; n++) {
            float qv = qs[c][n];
            #pragma unroll
            for (int j = 0; j < 4; j++) acc[j] += qv * ks[d0+j][n];
        }
        __syncthreads();
    }
    #pragma unroll
    for (int j = 0; j < 4; j++)
        atomicAdd(&g_gram[((size_t)bh*32 + c)*32 + d0 + j], acc[j]);
}

__global__ __launch_bounds__(256) void softfold(const float* __restrict__ temp,
                                                const float* __restrict__ proj)
{
    int bh = blockIdx.x;
    int b = bh / HEADS, h = bh % HEADS;
    __shared__ float attn[32][33];
    int tid = threadIdx.x;
    int wrp = tid >> 5, ln = tid & 31;
    float tmp = temp[h];
    for (int r = wrp; r < 32; r += 8) {
        float v = g_gram[((size_t)bh*32 + r)*32 + ln]
                * g_invq[b*C_ + h*32 + r] * g_invk[b*C_ + h*32 + ln] * tmp;
        float m = v;
        #pragma unroll
        for (int off = 16; off; off >>= 1) m = fmaxf(m, __shfl_xor_sync(0xffffffff, m, off));
        float e = expf(v - m);
        float s = e;
        #pragma unroll
        for (int off = 16; off; off >>= 1) s += __shfl_xor_sync(0xffffffff, s, off);
        attn[r][ln] = e / s;
    }
    __syncthreads();
    for (int l = tid; l < C_*32; l += 256) {
        int co = l >> 5, d = l & 31;
        float s = 0.f;
        #pragma unroll
        for (int cc = 0; cc < 32; cc++)
            s += proj[(size_t)co*C_ + h*32 + cc] * attn[cc][d];
        g_weff[((size_t)b*C_ + co)*C_ + h*32 + d] = s;
    }
}

// ------------------ launcher ------------------
extern "C" void kernel_launch(void* const* d_in, const int* in_sizes, int n_in,
                              void* d_out, int out_size)
{
    const float* x           = (const float*)d_in[0];
    const float* y           = (const float*)d_in[1];
    const float* q_w         = (const float*)d_in[2];
    const float* kv_w        = (const float*)d_in[3];
    const float* kvdw_w      = (const float*)d_in[4];
    const float* proj_w      = (const float*)d_in[5];
    const float* temperature = (const float*)d_in[6];

    float *p_kv, *p_kvd, *p_q, *p_invq, *p_invk;
    __half *p_xh,*p_xl,*p_yh,*p_yl,*p_vh,*p_vl,*p_kvwh,*p_kvwl,*p_qwh,*p_qwl,*p_wfh,*p_wfl;
    cudaGetSymbolAddress((void**)&p_kv, g_kv);   cudaGetSymbolAddress((void**)&p_kvd, g_kvd);
    cudaGetSymbolAddress((void**)&p_q, g_q);
    cudaGetSymbolAddress((void**)&p_invq, g_invq); cudaGetSymbolAddress((void**)&p_invk, g_invk);
    cudaGetSymbolAddress((void**)&p_xh, g_xh);   cudaGetSymbolAddress((void**)&p_xl, g_xl);
    cudaGetSymbolAddress((void**)&p_yh, g_yh);   cudaGetSymbolAddress((void**)&p_yl, g_yl);
    cudaGetSymbolAddress((void**)&p_vh, g_vh);   cudaGetSymbolAddress((void**)&p_vl, g_vl);
    cudaGetSymbolAddress((void**)&p_kvwh, g_kvwh); cudaGetSymbolAddress((void**)&p_kvwl, g_kvwl);
    cudaGetSymbolAddress((void**)&p_qwh, g_qwh); cudaGetSymbolAddress((void**)&p_qwl, g_qwl);
    cudaGetSymbolAddress((void**)&p_wfh, g_wfh); cudaGetSymbolAddress((void**)&p_wfl, g_wfl);

    const int SMEM128 = 163840;   // 2 stages x 80KB
    const int SMEM64  = 131072;   // 2 stages x 64KB
    cudaFuncSetAttribute(hgemm<1,128>, cudaFuncAttributeMaxDynamicSharedMemorySize, SMEM128);
    cudaFuncSetAttribute(hgemm<9,128>, cudaFuncAttributeMaxDynamicSharedMemorySize, SMEM128);
    cudaFuncSetAttribute(hgemm<1,64>,  cudaFuncAttributeMaxDynamicSharedMemorySize, SMEM64);
    cudaFuncSetAttribute(hgemm<9,64>,  cudaFuncAttributeMaxDynamicSharedMemorySize, SMEM64);

    dim3 tb(32,8);
    // prepack
    pack_kvw<<<(384*192+255)/256, 256>>>(kv_w, p_kvwh, p_kvwl);
    pack_qw <<<(256*9*192+255)/256, 256>>>(q_w, p_qwh, p_qwl);
    t32pad<<<dim3(HW_/32, C_/32, B_), tb>>>(x, p_xh, p_xl);
    zb<<<(B_*772*C_+255)/256, 256>>>(p_xh, p_xl);
    t32<<<dim3(HW_/32, C_/32, B_), tb>>>(y, (size_t)C_*HW_, p_yh, p_yl);

    // kv = kv_w(384x192) @ y  -> g_kv fp32   (M=384 = 3x128 exact)
    hgemm<1,128><<<dim3(HW_/NT, B_, 3), 256, SMEM128>>>(
        p_kvwh, p_kvwl, 0, p_yh, p_yl, (size_t)HW_*C_, (size_t)NT*C_,
        p_kv, (size_t)2*C_*HW_, 0, 384);

    // depthwise 3x3 -> g_kvd = [k|v]  (smem-tiled)
    dwconv_t<<<dim3(H_/32, 2*C_, B_), 256>>>(p_kv, kvdw_w, p_kvd);

    // q = conv3x3(x) via 9 shifted GEMMs  (M=192 = 128 + 64 exact)
    hgemm<9,128><<<dim3(H_, B_, 1), 256, SMEM128>>>(
        p_qwh, p_qwl, 0, p_xh, p_xl, (size_t)PW*PW*C_, (size_t)PW*C_,
        p_q, (size_t)C_*HW_, 0, C_);
    hgemm<9,64><<<dim3(H_, B_, 1), 256, SMEM64>>>(
        p_qwh, p_qwl, 0, p_xh, p_xl, (size_t)PW*PW*C_, (size_t)PW*C_,
        p_q, (size_t)C_*HW_, 128, C_);

    // v -> pixel-major fp16 hi/lo
    t32<<<dim3(HW_/32, C_/32, B_), tb>>>(p_kvd + (size_t)C_*HW_, (size_t)2*C_*HW_, p_vh, p_vl);

    invnorm<<<B_*C_, 256>>>(p_q,   C_,   p_invq);
    invnorm<<<B_*C_, 256>>>(p_kvd, 2*C_, p_invk);

    zero_gram<<<(B_*HEADS*32*32+255)/256, 256>>>();
    gram_kernel<<<dim3(8, B_*HEADS), 256>>>(p_q, p_kvd);
    softfold<<<B_*HEADS, 256>>>(temperature, proj_w);
    pack_weff<<<(B_*256*192+255)/256, 256>>>(p_wfh, p_wfl);

    // out = W_eff[b](192x192) @ v[b]   (M=192 = 128 + 64 exact)
    hgemm<1,128><<<dim3(HW_/NT, B_, 1), 256, SMEM128>>>(
        p_wfh, p_wfl, (size_t)256*192, p_vh, p_vl, (size_t)HW_*C_, (size_t)NT*C_,
        (float*)d_out, (size_t)C_*HW_, 0, C_);
    hgemm<1,64><<<dim3(HW_/NT, B_, 1), 256, SMEM64>>>(
        p_wfh, p_wfl, (size_t)256*192, p_vh, p_vl, (size_t)HW_*C_, (size_t)NT*C_,
        (float*)d_out, (size_t)C_*HW_, 128, C_);
}

// round 9
// speedup vs baseline: 4.5794x; 1.3348x over previous
#include <cuda_runtime.h>
#include <cuda_fp16.h>
#include <math.h>
#include <stdint.h>

#define B_ 4
#define C_ 192
#define H_ 192
#define W_ 192
#define HW_ (H_*W_)
#define HEADS 6
#define PW 194
#define KTOT 192
#define NT 192

// ------------------ scratch ------------------
__device__ __align__(128) __half g_xh[(size_t)B_*PW*PW*C_];
__device__ __align__(128) __half g_yh[(size_t)B_*HW_*C_],   g_yl[(size_t)B_*HW_*C_];
__device__ __align__(128) __half g_vh[(size_t)B_*HW_*C_],   g_vl[(size_t)B_*HW_*C_];
__device__ __align__(128) __half g_kvwh[384*192], g_kvwl[384*192];
__device__ __align__(128) __half g_qwh[256*9*192];
__device__ __align__(128) __half g_wfh[B_*256*192], g_wfl[B_*256*192];
__device__ __align__(128) float  g_kv [(size_t)B_*2*C_*HW_];
__device__ __align__(128) float  g_kvd[(size_t)B_*2*C_*HW_];
__device__ __align__(128) float  g_q  [(size_t)B_*C_*HW_];
__device__ __align__(128) float  g_invq[B_*C_], g_invk[B_*C_];
__device__ __align__(128) float  g_gram[B_*HEADS*32*32];
__device__ __align__(128) float  g_weff[(size_t)B_*C_*C_];

// ------------------ PTX helpers (baseline features only) ------------------
__device__ __forceinline__ uint32_t s2u(const void* p){
    uint32_t a;
    asm("{ .reg .u64 t; cvta.to.shared.u64 t, %1; cvt.u32.u64 %0, t; }":"=r"(a):"l"(p));
    return a;
}
#define SWZ(o) ((o) ^ (((o)>>3)&0x70))
__device__ __forceinline__ void cpa16(uint32_t d, const void* s){
    asm volatile("cp.async.cg.shared.global [%0], [%1], 16;"::"r"(d),"l"(s));
}
__device__ __forceinline__ void ldsm4(uint32_t* r, uint32_t a){
    asm volatile("ldmatrix.sync.aligned.m8n8.x4.shared.b16 {%0,%1,%2,%3}, [%4];"
        :"=r"(r[0]),"=r"(r[1]),"=r"(r[2]),"=r"(r[3]):"r"(a));
}
__device__ __forceinline__ void ldsm2(uint32_t* r, uint32_t a){
    asm volatile("ldmatrix.sync.aligned.m8n8.x2.shared.b16 {%0,%1}, [%2];"
        :"=r"(r[0]),"=r"(r[1]):"r"(a));
}
__device__ __forceinline__ void mma16816(float* c, const uint32_t* a, const uint32_t* b){
    asm volatile("mma.sync.aligned.m16n8k16.row.col.f32.f16.f16.f32 "
        "{%0,%1,%2,%3}, {%4,%5,%6,%7}, {%8,%9}, {%0,%1,%2,%3};"
        : "+f"(c[0]),"+f"(c[1]),"+f"(c[2]),"+f"(c[3])
        : "r"(a[0]),"r"(a[1]),"r"(a[2]),"r"(a[3]),"r"(b[0]),"r"(b[1]));
}

// ------------------ prepack kernels ------------------
__device__ __forceinline__ void split_h(float v, __half& h, __half& l){
    h = __float2half_rn(v);
    l = __float2half_rn(v - __half2float(h));
}

// fp32 [C][HW] -> fp16 hi/lo [HW][C] (pixel-major)
__global__ void t32(const float* __restrict__ src, size_t sBatch,
                    __half* __restrict__ dh, __half* __restrict__ dl)
{
    __shared__ float t[32][33];
    int p0 = blockIdx.x*32, c0 = blockIdx.y*32, b = blockIdx.z;
    const float* s = src + (size_t)b*sBatch;
    int tx = threadIdx.x, ty = threadIdx.y;
    #pragma unroll
    for (int j=0;j<4;j++)
        t[ty+8*j][tx] = s[(size_t)(c0+ty+8*j)*HW_ + p0+tx];
    __syncthreads();
    #pragma unroll
    for (int j=0;j<4;j++){
        __half hh,ll; split_h(t[tx][ty+8*j], hh, ll);
        size_t o = ((size_t)b*HW_ + p0+ty+8*j)*C_ + c0+tx;
        dh[o]=hh; dl[o]=ll;
    }
}

// fp32 x [C][HW] -> padded fp16 (hi only) [194][194][C]
__global__ void t32pad(const float* __restrict__ src, __half* __restrict__ dh)
{
    __shared__ float t[32][33];
    int p0 = blockIdx.x*32, c0 = blockIdx.y*32, b = blockIdx.z;
    const float* s = src + (size_t)b*C_*HW_;
    int tx = threadIdx.x, ty = threadIdx.y;
    #pragma unroll
    for (int j=0;j<4;j++)
        t[ty+8*j][tx] = s[(size_t)(c0+ty+8*j)*HW_ + p0+tx];
    __syncthreads();
    #pragma unroll
    for (int j=0;j<4;j++){
        int p = p0+ty+8*j, yy = p/W_, xx = p%W_;
        size_t o = ((size_t)b*PW*PW + (size_t)(yy+1)*PW + (xx+1))*C_ + c0+tx;
        dh[o] = __float2half_rn(t[tx][ty+8*j]);
    }
}

__global__ void zb(__half* __restrict__ dh)
{
    int i = blockIdx.x*256 + threadIdx.x;
    const int per_b = 772*C_;
    if (i >= B_*per_b) return;
    int b = i/per_b, rem = i%per_b, ridx = rem/C_, c = rem%C_;
    int yy, xx;
    if (ridx < 194)      { yy=0;   xx=ridx; }
    else if (ridx < 388) { yy=193; xx=ridx-194; }
    else if (ridx < 580) { yy=ridx-388+1; xx=0; }
    else                 { yy=ridx-580+1; xx=193; }
    size_t o = ((size_t)b*PW*PW + (size_t)yy*PW + xx)*C_ + c;
    dh[o] = __float2half_rn(0.f);
}

__global__ void pack_kvw(const float* __restrict__ w,
                         __half* __restrict__ h, __half* __restrict__ l)
{
    int i = blockIdx.x*256 + threadIdx.x;
    if (i >= 384*192) return;
    __half hh,ll; split_h(w[i], hh, ll); h[i]=hh; l[i]=ll;
}

// q_w [192][192][3][3] -> [256][9][192] (hi only), oc>=192 zero
__global__ void pack_qw(const float* __restrict__ w, __half* __restrict__ h)
{
    int i = blockIdx.x*256 + threadIdx.x;
    if (i >= 256*9*192) return;
    int oc = i/(9*192), rem = i%(9*192), t = rem/192, ic = rem%192;
    float v = (oc < 192) ? w[((size_t)(oc*192+ic))*9 + t] : 0.f;
    h[i] = __float2half_rn(v);
}

// g_weff fp32 [b][192][192] -> hi/lo [b][256][192], rows>=192 zero
__global__ void pack_weff(__half* __restrict__ h, __half* __restrict__ l)
{
    int i = blockIdx.x*256 + threadIdx.x;
    if (i >= B_*256*192) return;
    int b = i/(256*192), rem = i%(256*192), r = rem/192, c = rem%192;
    float v = (r < 192) ? g_weff[((size_t)b*C_ + r)*C_ + c] : 0.f;
    __half hh,ll; split_h(v, hh, ll); h[i]=hh; l[i]=ll;
}

// ------------------ warp-MMA GEMM / conv (mma.sync, double-buffered) ---------
// Block tile BM x 192. 256 thr = 8 warps (2m x 4n).
// TERMS=3: hi/lo split (AhBh+AhBl+AlBh). TERMS=1: plain fp16 (AhBh).
template<int TAPS, int BM, int TERMS>
__global__ __launch_bounds__(256,1) void hgemm(
    const __half* __restrict__ Ah, const __half* __restrict__ Al, size_t aBatch,
    const __half* __restrict__ Bh, const __half* __restrict__ Bl, size_t bBatch,
    size_t bRowStride, float* __restrict__ out, size_t oBatch,
    int m0base, int M_real)
{
    constexpr int MT = BM/32;
    constexpr uint32_t ASZ  = (uint32_t)BM*128u;
    constexpr uint32_t BOFF = (TERMS==3 ? 2u : 1u)*ASZ;
    constexpr uint32_t STG  = BOFF + (TERMS==3 ? 49152u : 24576u);
    extern __shared__ char smem[];
    uint32_t sb = s2u(smem);
    const int NC = 3*TAPS;
    int tid = threadIdx.x, lane = tid&31, wid = tid>>5;
    int wm = wid&1, wn = wid>>1;
    int bx = blockIdx.x, b = blockIdx.y;
    int m0 = m0base + blockIdx.z*BM;
    const __half* Ahb = Ah + (size_t)b*aBatch;
    const __half* Alb = (TERMS==3) ? Al + (size_t)b*aBatch : nullptr;
    const __half* Bhb = Bh + (size_t)b*bBatch + (size_t)bx*bRowStride;
    const __half* Blb = (TERMS==3) ? Bl + (size_t)b*bBatch + (size_t)bx*bRowStride : nullptr;

    auto load = [&](int it){
        uint32_t base = sb + (uint32_t)(it&1)*STG;
        int tap = (TAPS==9)? it/3 : 0;
        int kc  = (TAPS==9)? it%3 : it;
        size_t tapOff = (TAPS==9)? (size_t)((tap/3)*PW + (tap%3))*C_ : 0;
        #pragma unroll
        for (int i=0;i<BM/32;i++){
            int idx = tid + i*256; int r = idx>>3, j = idx&7;
            size_t ge = (size_t)(m0+r)*((size_t)TAPS*KTOT) + (size_t)tap*KTOT + kc*64;
            uint32_t off = SWZ((uint32_t)(r*128 + j*16));
            cpa16(base + 0u + off, (const char*)(Ahb+ge) + j*16);
            if (TERMS==3) cpa16(base + ASZ + off, (const char*)(Alb+ge) + j*16);
        }
        #pragma unroll
        for (int i=0;i<6;i++){
            int idx = tid + i*256; int r = idx>>3, j = idx&7;
            size_t ge = tapOff + (size_t)r*KTOT + kc*64;
            uint32_t off = SWZ((uint32_t)(r*128 + j*16));
            cpa16(base + BOFF + off, (const char*)(Bhb+ge) + j*16);
            if (TERMS==3) cpa16(base + BOFF + 24576u + off, (const char*)(Blb+ge) + j*16);
        }
        asm volatile("cp.async.commit_group;":::"memory");
    };

    float acc[MT][6][4] = {};

    load(0);
    #pragma unroll 1
    for (int it=0; it<NC; it++){
        if (it+1 < NC){
            load(it+1);
            asm volatile("cp.async.wait_group 1;":::"memory");
        } else {
            asm volatile("cp.async.wait_group 0;":::"memory");
        }
        __syncthreads();
        uint32_t base = sb + (uint32_t)(it&1)*STG;
        #pragma unroll
        for (int kk=0;kk<4;kk++){
            uint32_t ah[MT][4], al[MT][4], bh[6][2], bl[6][2];
            #pragma unroll
            for (int mt=0;mt<MT;mt++){
                int row = wm*(MT*16) + mt*16 + (lane&15);
                uint32_t off = SWZ((uint32_t)(row*128 + (2*kk + (lane>>4))*16));
                ldsm4(ah[mt], base + 0u + off);
                if (TERMS==3) ldsm4(al[mt], base + ASZ + off);
            }
            #pragma unroll
            for (int nt=0;nt<6;nt++){
                int rn = wn*48 + nt*8 + (lane&7);
                uint32_t off = SWZ((uint32_t)(rn*128 + (2*kk + ((lane>>3)&1))*16));
                ldsm2(bh[nt], base + BOFF + off);
                if (TERMS==3) ldsm2(bl[nt], base + BOFF + 24576u + off);
            }
            #pragma unroll
            for (int mt=0;mt<MT;mt++)
                #pragma unroll
                for (int nt=0;nt<6;nt++){
                    mma16816(acc[mt][nt], ah[mt], bh[nt]);
                    if (TERMS==3){
                        mma16816(acc[mt][nt], ah[mt], bl[nt]);
                        mma16816(acc[mt][nt], al[mt], bh[nt]);
                    }
                }
        }
        __syncthreads();
    }

    #pragma unroll
    for (int mt=0;mt<MT;mt++){
        int row = m0 + wm*(MT*16) + mt*16 + (lane>>2);
        #pragma unroll
        for (int nt=0;nt<6;nt++){
            int col = bx*NT + wn*48 + nt*8 + (lane&3)*2;
            if (row < M_real){
                float2* p = (float2*)(out + (size_t)b*oBatch + (size_t)row*HW_ + col);
                *p = make_float2(acc[mt][nt][0], acc[mt][nt][1]);
            }
            if (row+8 < M_real){
                float2* p = (float2*)(out + (size_t)b*oBatch + (size_t)(row+8)*HW_ + col);
                *p = make_float2(acc[mt][nt][2], acc[mt][nt][3]);
            }
        }
    }
}

// ------------------ depthwise 3x3, smem-tiled ------------------
__global__ __launch_bounds__(256) void dwconv_t(const float* __restrict__ in,
                                                const float* __restrict__ w,
                                                float* __restrict__ out)
{
    __shared__ float s[34][196];
    int y0 = blockIdx.x*32;
    int ch = blockIdx.y;
    int b  = blockIdx.z;
    int tid = threadIdx.x;
    const float* src = in + ((size_t)b*2*C_ + ch)*HW_;
    for (int l = tid; l < 34*194; l += 256){
        int r = l/194, c = l%194;
        int gy = y0 + r - 1, gx = c - 1;
        float v = 0.f;
        if ((unsigned)gy < (unsigned)H_ && (unsigned)gx < (unsigned)W_)
            v = src[(size_t)gy*W_ + gx];
        s[r][c] = v;
    }
    float w0=w[ch*9+0], w1=w[ch*9+1], w2=w[ch*9+2],
          w3=w[ch*9+3], w4=w[ch*9+4], w5=w[ch*9+5],
          w6=w[ch*9+6], w7=w[ch*9+7], w8=w[ch*9+8];
    __syncthreads();
    float* dst = out + ((size_t)b*2*C_ + ch)*HW_ + (size_t)y0*W_;
    for (int l = tid; l < 32*192; l += 256){
        int r = l/192, c = l%192;
        float acc = w0*s[r  ][c] + w1*s[r  ][c+1] + w2*s[r  ][c+2]
                  + w3*s[r+1][c] + w4*s[r+1][c+1] + w5*s[r+1][c+2]
                  + w6*s[r+2][c] + w7*s[r+2][c+1] + w8*s[r+2][c+2];
        dst[(size_t)r*W_ + c] = acc;
    }
}

// ------------------ fp32 tail kernels ------------------
__global__ __launch_bounds__(256) void invnorm(const float* __restrict__ src,
                                               int chanPerB, float* __restrict__ dst)
{
    int bc = blockIdx.x;
    int b = bc / C_, c = bc % C_;
    const float4* p = reinterpret_cast<const float4*>(src + ((size_t)b*chanPerB + c)*HW_);
    float ss = 0.f;
    for (int i = threadIdx.x; i < HW_/4; i += 256) {
        float4 v = p[i];
        ss += v.x*v.x + v.y*v.y + v.z*v.z + v.w*v.w;
    }
    #pragma unroll
    for (int off = 16; off; off >>= 1) ss += __shfl_xor_sync(0xffffffff, ss, off);
    __shared__ float red[8];
    if ((threadIdx.x & 31) == 0) red[threadIdx.x >> 5] = ss;
    __syncthreads();
    if (threadIdx.x == 0) {
        float t = 0.f;
        #pragma unroll
        for (int i = 0; i < 8; i++) t += red[i];
        dst[bc] = 1.f / fmaxf(sqrtf(t), 1e-12f);
    }
}

__global__ void zero_gram()
{
    int i = blockIdx.x * 256 + threadIdx.x;
    if (i < B_*HEADS*32*32) g_gram[i] = 0.f;
}

__global__ __launch_bounds__(256) void gram_kernel(const float* __restrict__ q,
                                                   const float* __restrict__ kk)
{
    int split = blockIdx.x;
    int bh = blockIdx.y;
    int b = bh / HEADS, h = bh % HEADS;
    __shared__ float qs[32][65], ks[32][65];
    const float* qb = q  + ((size_t)b*C_   + h*32)*HW_;
    const float* kb = kk + ((size_t)b*2*C_ + h*32)*HW_;
    int n0 = split * (HW_/8);
    int tid = threadIdx.x;
    int c = tid >> 3, d0 = (tid & 7) << 2;
    float acc[4] = {0.f, 0.f, 0.f, 0.f};
    for (int nt = 0; nt < HW_/8; nt += 64) {
        for (int l = tid; l < 2048; l += 256) {
            int cc = l >> 6, nn = l & 63;
            size_t off = (size_t)cc*HW_ + n0 + nt + nn;
            qs[cc][nn] = qb[off];
            ks[cc][nn] = kb[off];
        }
        __syncthreads();
        #pragma unroll 8
        for (int n = 0; n < 64; n++) {
            float qv = qs[c][n];
            #pragma unroll
            for (int j = 0; j < 4; j++) acc[j] += qv * ks[d0+j][n];
        }
        __syncthreads();
    }
    #pragma unroll
    for (int j = 0; j < 4; j++)
        atomicAdd(&g_gram[((size_t)bh*32 + c)*32 + d0 + j], acc[j]);
}

__global__ __launch_bounds__(256) void softfold(const float* __restrict__ temp,
                                                const float* __restrict__ proj)
{
    int bh = blockIdx.x;
    int b = bh / HEADS, h = bh % HEADS;
    __shared__ float attn[32][33];
    int tid = threadIdx.x;
    int wrp = tid >> 5, ln = tid & 31;
    float tmp = temp[h];
    for (int r = wrp; r < 32; r += 8) {
        float v = g_gram[((size_t)bh*32 + r)*32 + ln]
                * g_invq[b*C_ + h*32 + r] * g_invk[b*C_ + h*32 + ln] * tmp;
        float m = v;
        #pragma unroll
        for (int off = 16; off; off >>= 1) m = fmaxf(m, __shfl_xor_sync(0xffffffff, m, off));
        float e = expf(v - m);
        float s = e;
        #pragma unroll
        for (int off = 16; off; off >>= 1) s += __shfl_xor_sync(0xffffffff, s, off);
        attn[r][ln] = e / s;
    }
    __syncthreads();
    for (int l = tid; l < C_*32; l += 256) {
        int co = l >> 5, d = l & 31;
        float s = 0.f;
        #pragma unroll
        for (int cc = 0; cc < 32; cc++)
            s += proj[(size_t)co*C_ + h*32 + cc] * attn[cc][d];
        g_weff[((size_t)b*C_ + co)*C_ + h*32 + d] = s;
    }
}

// ------------------ launcher ------------------
extern "C" void kernel_launch(void* const* d_in, const int* in_sizes, int n_in,
                              void* d_out, int out_size)
{
    const float* x           = (const float*)d_in[0];
    const float* y           = (const float*)d_in[1];
    const float* q_w         = (const float*)d_in[2];
    const float* kv_w        = (const float*)d_in[3];
    const float* kvdw_w      = (const float*)d_in[4];
    const float* proj_w      = (const float*)d_in[5];
    const float* temperature = (const float*)d_in[6];

    float *p_kv, *p_kvd, *p_q, *p_invq, *p_invk;
    __half *p_xh,*p_yh,*p_yl,*p_vh,*p_vl,*p_kvwh,*p_kvwl,*p_qwh,*p_wfh,*p_wfl;
    cudaGetSymbolAddress((void**)&p_kv, g_kv);   cudaGetSymbolAddress((void**)&p_kvd, g_kvd);
    cudaGetSymbolAddress((void**)&p_q, g_q);
    cudaGetSymbolAddress((void**)&p_invq, g_invq); cudaGetSymbolAddress((void**)&p_invk, g_invk);
    cudaGetSymbolAddress((void**)&p_xh, g_xh);
    cudaGetSymbolAddress((void**)&p_yh, g_yh);   cudaGetSymbolAddress((void**)&p_yl, g_yl);
    cudaGetSymbolAddress((void**)&p_vh, g_vh);   cudaGetSymbolAddress((void**)&p_vl, g_vl);
    cudaGetSymbolAddress((void**)&p_kvwh, g_kvwh); cudaGetSymbolAddress((void**)&p_kvwl, g_kvwl);
    cudaGetSymbolAddress((void**)&p_qwh, g_qwh);
    cudaGetSymbolAddress((void**)&p_wfh, g_wfh); cudaGetSymbolAddress((void**)&p_wfl, g_wfl);

    const int SM_T3_128 = 163840, SM_T3_64 = 131072;
    const int SM_T1_128 = 81920,  SM_T1_64 = 65536;
    cudaFuncSetAttribute(hgemm<9,128,1>, cudaFuncAttributeMaxDynamicSharedMemorySize, SM_T1_128);
    cudaFuncSetAttribute(hgemm<9,64,1>,  cudaFuncAttributeMaxDynamicSharedMemorySize, SM_T1_64);
    cudaFuncSetAttribute(hgemm<1,128,1>, cudaFuncAttributeMaxDynamicSharedMemorySize, SM_T1_128);
    cudaFuncSetAttribute(hgemm<1,64,1>,  cudaFuncAttributeMaxDynamicSharedMemorySize, SM_T1_64);
    cudaFuncSetAttribute(hgemm<1,128,3>, cudaFuncAttributeMaxDynamicSharedMemorySize, SM_T3_128);
    cudaFuncSetAttribute(hgemm<1,64,3>,  cudaFuncAttributeMaxDynamicSharedMemorySize, SM_T3_64);

    dim3 tb(32,8);
    // prepack
    pack_kvw<<<(384*192+255)/256, 256>>>(kv_w, p_kvwh, p_kvwl);
    pack_qw <<<(256*9*192+255)/256, 256>>>(q_w, p_qwh);
    t32pad<<<dim3(HW_/32, C_/32, B_), tb>>>(x, p_xh);
    zb<<<(B_*772*C_+255)/256, 256>>>(p_xh);
    t32<<<dim3(HW_/32, C_/32, B_), tb>>>(y, (size_t)C_*HW_, p_yh, p_yl);

    // k = kv_w[0:192] @ y  (1-term fp16; error attenuated through softmax)
    hgemm<1,128,1><<<dim3(HW_/NT, B_, 1), 256, SM_T1_128>>>(
        p_kvwh, nullptr, 0, p_yh, nullptr, (size_t)HW_*C_, (size_t)NT*C_,
        p_kv, (size_t)2*C_*HW_, 0, C_);
    hgemm<1,64,1><<<dim3(HW_/NT, B_, 1), 256, SM_T1_64>>>(
        p_kvwh, nullptr, 0, p_yh, nullptr, (size_t)HW_*C_, (size_t)NT*C_,
        p_kv, (size_t)2*C_*HW_, 128, C_);

    // v = kv_w[192:384] @ y  (3-term: precision-critical, output is linear in v)
    hgemm<1,128,3><<<dim3(HW_/NT, B_, 1), 256, SM_T3_128>>>(
        p_kvwh + (size_t)192*192, p_kvwl + (size_t)192*192, 0,
        p_yh, p_yl, (size_t)HW_*C_, (size_t)NT*C_,
        p_kv + (size_t)C_*HW_, (size_t)2*C_*HW_, 0, C_);
    hgemm<1,64,3><<<dim3(HW_/NT, B_, 1), 256, SM_T3_64>>>(
        p_kvwh + (size_t)192*192, p_kvwl + (size_t)192*192, 0,
        p_yh, p_yl, (size_t)HW_*C_, (size_t)NT*C_,
        p_kv + (size_t)C_*HW_, (size_t)2*C_*HW_, 128, C_);

    // depthwise 3x3 -> g_kvd = [k|v]
    dwconv_t<<<dim3(H_/32, 2*C_, B_), 256>>>(p_kv, kvdw_w, p_kvd);

    // q = conv3x3(x) via 9 shifted GEMMs (1-term fp16)
    hgemm<9,128,1><<<dim3(H_, B_, 1), 256, SM_T1_128>>>(
        p_qwh, nullptr, 0, p_xh, nullptr, (size_t)PW*PW*C_, (size_t)PW*C_,
        p_q, (size_t)C_*HW_, 0, C_);
    hgemm<9,64,1><<<dim3(H_, B_, 1), 256, SM_T1_64>>>(
        p_qwh, nullptr, 0, p_xh, nullptr, (size_t)PW*PW*C_, (size_t)PW*C_,
        p_q, (size_t)C_*HW_, 128, C_);

    // v -> pixel-major fp16 hi/lo
    t32<<<dim3(HW_/32, C_/32, B_), tb>>>(p_kvd + (size_t)C_*HW_, (size_t)2*C_*HW_, p_vh, p_vl);

    invnorm<<<B_*C_, 256>>>(p_q,   C_,   p_invq);
    invnorm<<<B_*C_, 256>>>(p_kvd, 2*C_, p_invk);

    zero_gram<<<(B_*HEADS*32*32+255)/256, 256>>>();
    gram_kernel<<<dim3(8, B_*HEADS), 256>>>(p_q, p_kvd);
    softfold<<<B_*HEADS, 256>>>(temperature, proj_w);
    pack_weff<<<(B_*256*192+255)/256, 256>>>(p_wfh, p_wfl);

    // out = W_eff[b](192x192) @ v[b]  (3-term)
    hgemm<1,128,3><<<dim3(HW_/NT, B_, 1), 256, SM_T3_128>>>(
        p_wfh, p_wfl, (size_t)256*192, p_vh, p_vl, (size_t)HW_*C_, (size_t)NT*C_,
        (float*)d_out, (size_t)C_*HW_, 0, C_);
    hgemm<1,64,3><<<dim3(HW_/NT, B_, 1), 256, SM_T3_64>>>(
        p_wfh, p_wfl, (size_t)256*192, p_vh, p_vl, (size_t)HW_*C_, (size_t)NT*C_,
        (float*)d_out, (size_t)C_*HW_, 128, C_);
}

// round 13
// speedup vs baseline: 4.7655x; 1.0406x over previous
#include <cuda_runtime.h>
#include <cuda_fp16.h>
#include <math.h>
#include <stdint.h>

#define B_ 4
#define C_ 192
#define H_ 192
#define W_ 192
#define HW_ (H_*W_)
#define HEADS 6
#define PW 194
#define KTOT 192
#define NT 192

// ------------------ scratch ------------------
__device__ __align__(128) __half g_xh[(size_t)B_*PW*PW*C_];
__device__ __align__(128) __half g_yh[(size_t)B_*HW_*C_],   g_yl[(size_t)B_*HW_*C_];
__device__ __align__(128) __half g_vh[(size_t)B_*HW_*C_],   g_vl[(size_t)B_*HW_*C_];
__device__ __align__(128) __half g_kvwh[384*192], g_kvwl[384*192];
__device__ __align__(128) __half g_qwh[192*9*192];
__device__ __align__(128) __half g_wfh[B_*192*192], g_wfl[B_*192*192];
__device__ __align__(128) float  g_kv [(size_t)B_*2*C_*HW_];
__device__ __align__(128) float  g_kvd[(size_t)B_*2*C_*HW_];
__device__ __align__(128) float  g_q  [(size_t)B_*C_*HW_];
__device__ __align__(128) float  g_gram[B_*HEADS*32*32];
__device__ __align__(128) float  g_qss[B_*C_], g_kss[B_*C_];
__device__ __align__(128) float  g_weff[(size_t)B_*C_*C_];

// ------------------ PTX helpers (baseline features only) ------------------
__device__ __forceinline__ uint32_t s2u(const void* p){
    uint32_t a;
    asm("{ .reg .u64 t; cvta.to.shared.u64 t, %1; cvt.u32.u64 %0, t; }":"=r"(a):"l"(p));
    return a;
}
#define SWZ(o) ((o) ^ (((o)>>3)&0x70))
__device__ __forceinline__ void cpa16(uint32_t d, const void* s){
    asm volatile("cp.async.cg.shared.global [%0], [%1], 16;"::"r"(d),"l"(s));
}
__device__ __forceinline__ void ldsm4(uint32_t* r, uint32_t a){
    asm volatile("ldmatrix.sync.aligned.m8n8.x4.shared.b16 {%0,%1,%2,%3}, [%4];"
        :"=r"(r[0]),"=r"(r[1]),"=r"(r[2]),"=r"(r[3]):"r"(a));
}
__device__ __forceinline__ void ldsm2(uint32_t* r, uint32_t a){
    asm volatile("ldmatrix.sync.aligned.m8n8.x2.shared.b16 {%0,%1}, [%2];"
        :"=r"(r[0]),"=r"(r[1]):"r"(a));
}
__device__ __forceinline__ void mma16816(float* c, const uint32_t* a, const uint32_t* b){
    asm volatile("mma.sync.aligned.m16n8k16.row.col.f32.f16.f16.f32 "
        "{%0,%1,%2,%3}, {%4,%5,%6,%7}, {%8,%9}, {%0,%1,%2,%3};"
        : "+f"(c[0]),"+f"(c[1]),"+f"(c[2]),"+f"(c[3])
        : "r"(a[0]),"r"(a[1]),"r"(a[2]),"r"(a[3]),"r"(b[0]),"r"(b[1]));
}

// ------------------ prepack kernels ------------------
__device__ __forceinline__ void split_h(float v, __half& h, __half& l){
    h = __float2half_rn(v);
    l = __float2half_rn(v - __half2float(h));
}

// fp32 [C][HW] -> fp16 hi/lo [HW][C] (pixel-major)
__global__ void t32(const float* __restrict__ src, size_t sBatch,
                    __half* __restrict__ dh, __half* __restrict__ dl)
{
    __shared__ float t[32][33];
    int p0 = blockIdx.x*32, c0 = blockIdx.y*32, b = blockIdx.z;
    const float* s = src + (size_t)b*sBatch;
    int tx = threadIdx.x, ty = threadIdx.y;
    #pragma unroll
    for (int j=0;j<4;j++)
        t[ty+8*j][tx] = s[(size_t)(c0+ty+8*j)*HW_ + p0+tx];
    __syncthreads();
    #pragma unroll
    for (int j=0;j<4;j++){
        __half hh,ll; split_h(t[tx][ty+8*j], hh, ll);
        size_t o = ((size_t)b*HW_ + p0+ty+8*j)*C_ + c0+tx;
        dh[o]=hh; dl[o]=ll;
    }
}

// fp32 x [C][HW] -> padded fp16 (hi only) [194][194][C]
__global__ void t32pad(const float* __restrict__ src, __half* __restrict__ dh)
{
    __shared__ float t[32][33];
    int p0 = blockIdx.x*32, c0 = blockIdx.y*32, b = blockIdx.z;
    const float* s = src + (size_t)b*C_*HW_;
    int tx = threadIdx.x, ty = threadIdx.y;
    #pragma unroll
    for (int j=0;j<4;j++)
        t[ty+8*j][tx] = s[(size_t)(c0+ty+8*j)*HW_ + p0+tx];
    __syncthreads();
    #pragma unroll
    for (int j=0;j<4;j++){
        int p = p0+ty+8*j, yy = p/W_, xx = p%W_;
        size_t o = ((size_t)b*PW*PW + (size_t)(yy+1)*PW + (xx+1))*C_ + c0+tx;
        dh[o] = __float2half_rn(t[tx][ty+8*j]);
    }
}

__global__ void zb(__half* __restrict__ dh)
{
    int i = blockIdx.x*256 + threadIdx.x;
    const int per_b = 772*C_;
    if (i >= B_*per_b) return;
    int b = i/per_b, rem = i%per_b, ridx = rem/C_, c = rem%C_;
    int yy, xx;
    if (ridx < 194)      { yy=0;   xx=ridx; }
    else if (ridx < 388) { yy=193; xx=ridx-194; }
    else if (ridx < 580) { yy=ridx-388+1; xx=0; }
    else                 { yy=ridx-580+1; xx=193; }
    size_t o = ((size_t)b*PW*PW + (size_t)yy*PW + xx)*C_ + c;
    dh[o] = __float2half_rn(0.f);
}

__global__ void pack_kvw(const float* __restrict__ w,
                         __half* __restrict__ h, __half* __restrict__ l)
{
    int i = blockIdx.x*256 + threadIdx.x;
    if (i >= 384*192) return;
    __half hh,ll; split_h(w[i], hh, ll); h[i]=hh; l[i]=ll;
}

// q_w [192][192][3][3] -> [192][9][192] (hi only)
__global__ void pack_qw(const float* __restrict__ w, __half* __restrict__ h)
{
    int i = blockIdx.x*256 + threadIdx.x;
    if (i >= 192*9*192) return;
    int oc = i/(9*192), rem = i%(9*192), t = rem/192, ic = rem%192;
    h[i] = __float2half_rn(w[((size_t)(oc*192+ic))*9 + t]);
}

// g_weff fp32 [b][192][192] -> hi/lo [b][192][192]
__global__ void pack_weff(__half* __restrict__ h, __half* __restrict__ l)
{
    int i = blockIdx.x*256 + threadIdx.x;
    if (i >= B_*192*192) return;
    __half hh,ll; split_h(g_weff[i], hh, ll); h[i]=hh; l[i]=ll;
}

// ------------------ warp-MMA GEMM / conv: BM=192, 384 thr (12 warps 3m x 4n) --
// Y[b](192 x 192-tile) = sum_{tap,K} A[b] * B[b]^T.  M always exactly 192.
// TERMS=3: hi/lo split (AhBh+AhBl+AlBh). TERMS=1: plain fp16.
template<int TAPS, int TERMS>
__global__ __launch_bounds__(384,1) void hgemm(
    const __half* __restrict__ Ah, const __half* __restrict__ Al, size_t aBatch,
    const __half* __restrict__ Bh, const __half* __restrict__ Bl, size_t bBatch,
    size_t bRowStride, float* __restrict__ out, size_t oBatch)
{
    constexpr uint32_t ASZ  = 192u*128u;                    // 24576
    constexpr uint32_t BOFF = (TERMS==3 ? 2u : 1u)*ASZ;
    constexpr uint32_t STG  = BOFF + (TERMS==3 ? 2u : 1u)*24576u;
    extern __shared__ char smem[];
    uint32_t sb = s2u(smem);
    const int NC = 3*TAPS;
    int tid = threadIdx.x, lane = tid&31, wid = tid>>5;
    int wm = wid>>2, wn = wid&3;                            // 3 x 4
    int bx = blockIdx.x, b = blockIdx.y;
    const __half* Ahb = Ah + (size_t)b*aBatch;
    const __half* Alb = (TERMS==3) ? Al + (size_t)b*aBatch : nullptr;
    const __half* Bhb = Bh + (size_t)b*bBatch + (size_t)bx*bRowStride;
    const __half* Blb = (TERMS==3) ? Bl + (size_t)b*bBatch + (size_t)bx*bRowStride : nullptr;

    auto load = [&](int it){
        uint32_t base = sb + (uint32_t)(it&1)*STG;
        int tap = (TAPS==9)? it/3 : 0;
        int kc  = (TAPS==9)? it%3 : it;
        size_t tapOff = (TAPS==9)? (size_t)((tap/3)*PW + (tap%3))*C_ : 0;
        #pragma unroll
        for (int i=0;i<4;i++){                     // A: 192 rows x 8 x 16B
            int idx = tid + i*384; int r = idx>>3, j = idx&7;
            size_t ge = (size_t)r*((size_t)TAPS*KTOT) + (size_t)tap*KTOT + kc*64;
            uint32_t off = SWZ((uint32_t)(r*128 + j*16));
            cpa16(base + 0u + off, (const char*)(Ahb+ge) + j*16);
            if (TERMS==3) cpa16(base + ASZ + off, (const char*)(Alb+ge) + j*16);
        }
        #pragma unroll
        for (int i=0;i<4;i++){                     // B: 192 rows x 8 x 16B
            int idx = tid + i*384; int r = idx>>3, j = idx&7;
            size_t ge = tapOff + (size_t)r*KTOT + kc*64;
            uint32_t off = SWZ((uint32_t)(r*128 + j*16));
            cpa16(base + BOFF + off, (const char*)(Bhb+ge) + j*16);
            if (TERMS==3) cpa16(base + BOFF + 24576u + off, (const char*)(Blb+ge) + j*16);
        }
        asm volatile("cp.async.commit_group;":::"memory");
    };

    float acc[4][6][4] = {};

    load(0);
    #pragma unroll 1
    for (int it=0; it<NC; it++){
        if (it+1 < NC){
            load(it+1);
            asm volatile("cp.async.wait_group 1;":::"memory");
        } else {
            asm volatile("cp.async.wait_group 0;":::"memory");
        }
        __syncthreads();
        uint32_t base = sb + (uint32_t)(it&1)*STG;
        #pragma unroll
        for (int kk=0;kk<4;kk++){
            uint32_t ah[4][4], al[4][4], bh[6][2], bl[6][2];
            #pragma unroll
            for (int mt=0;mt<4;mt++){
                int row = wm*64 + mt*16 + (lane&15);
                uint32_t off = SWZ((uint32_t)(row*128 + (2*kk + (lane>>4))*16));
                ldsm4(ah[mt], base + 0u + off);
                if (TERMS==3) ldsm4(al[mt], base + ASZ + off);
            }
            #pragma unroll
            for (int nt=0;nt<6;nt++){
                int rn = wn*48 + nt*8 + (lane&7);
                uint32_t off = SWZ((uint32_t)(rn*128 + (2*kk + ((lane>>3)&1))*16));
                ldsm2(bh[nt], base + BOFF + off);
                if (TERMS==3) ldsm2(bl[nt], base + BOFF + 24576u + off);
            }
            #pragma unroll
            for (int mt=0;mt<4;mt++)
                #pragma unroll
                for (int nt=0;nt<6;nt++){
                    mma16816(acc[mt][nt], ah[mt], bh[nt]);
                    if (TERMS==3){
                        mma16816(acc[mt][nt], ah[mt], bl[nt]);
                        mma16816(acc[mt][nt], al[mt], bh[nt]);
                    }
                }
        }
        __syncthreads();
    }

    #pragma unroll
    for (int mt=0;mt<4;mt++){
        int row = wm*64 + mt*16 + (lane>>2);
        #pragma unroll
        for (int nt=0;nt<6;nt++){
            int col = bx*NT + wn*48 + nt*8 + (lane&3)*2;
            float2* p0 = (float2*)(out + (size_t)b*oBatch + (size_t)row*HW_ + col);
            *p0 = make_float2(acc[mt][nt][0], acc[mt][nt][1]);
            float2* p1 = (float2*)(out + (size_t)b*oBatch + (size_t)(row+8)*HW_ + col);
            *p1 = make_float2(acc[mt][nt][2], acc[mt][nt][3]);
        }
    }
}

// ------------------ depthwise 3x3, smem-tiled ------------------
__global__ __launch_bounds__(256) void dwconv_t(const float* __restrict__ in,
                                                const float* __restrict__ w,
                                                float* __restrict__ out)
{
    __shared__ float s[34][196];
    int y0 = blockIdx.x*32;
    int ch = blockIdx.y;
    int b  = blockIdx.z;
    int tid = threadIdx.x;
    const float* src = in + ((size_t)b*2*C_ + ch)*HW_;
    for (int l = tid; l < 34*194; l += 256){
        int r = l/194, c = l%194;
        int gy = y0 + r - 1, gx = c - 1;
        float v = 0.f;
        if ((unsigned)gy < (unsigned)H_ && (unsigned)gx < (unsigned)W_)
            v = src[(size_t)gy*W_ + gx];
        s[r][c] = v;
    }
    float w0=w[ch*9+0], w1=w[ch*9+1], w2=w[ch*9+2],
          w3=w[ch*9+3], w4=w[ch*9+4], w5=w[ch*9+5],
          w6=w[ch*9+6], w7=w[ch*9+7], w8=w[ch*9+8];
    __syncthreads();
    float* dst = out + ((size_t)b*2*C_ + ch)*HW_ + (size_t)y0*W_;
    for (int l = tid; l < 32*192; l += 256){
        int r = l/192, c = l%192;
        float acc = w0*s[r  ][c] + w1*s[r  ][c+1] + w2*s[r  ][c+2]
                  + w3*s[r+1][c] + w4*s[r+1][c+1] + w5*s[r+1][c+2]
                  + w6*s[r+2][c] + w7*s[r+2][c+1] + w8*s[r+2][c+2];
        dst[(size_t)r*W_ + c] = acc;
    }
}

// ------------------ gram + fused channel sum-of-squares ------------------
__global__ void zero_acc()
{
    int i = blockIdx.x * 256 + threadIdx.x;
    if (i < B_*HEADS*32*32) g_gram[i] = 0.f;
    else if (i < B_*HEADS*32*32 + B_*C_) g_qss[i - B_*HEADS*32*32] = 0.f;
    else if (i < B_*HEADS*32*32 + 2*B_*C_) g_kss[i - B_*HEADS*32*32 - B_*C_] = 0.f;
}

__global__ __launch_bounds__(256) void gram_kernel(const float* __restrict__ q,
                                                   const float* __restrict__ kk)
{
    int split = blockIdx.x;
    int bh = blockIdx.y;
    int b = bh / HEADS, h = bh % HEADS;
    __shared__ float qs[32][65], ks[32][65];
    const float* qb = q  + ((size_t)b*C_   + h*32)*HW_;
    const float* kb = kk + ((size_t)b*2*C_ + h*32)*HW_;
    int n0 = split * (HW_/8);
    int tid = threadIdx.x;
    int c = tid >> 3, d0 = (tid & 7) << 2;
    int sub = tid & 7;
    float acc[4] = {0.f, 0.f, 0.f, 0.f};
    float ssq = 0.f;   // sub==0: sum q[c]^2 ; sub==1: sum k[c]^2
    for (int nt = 0; nt < HW_/8; nt += 64) {
        for (int l = tid; l < 2048; l += 256) {
            int cc = l >> 6, nn = l & 63;
            size_t off = (size_t)cc*HW_ + n0 + nt + nn;
            qs[cc][nn] = qb[off];
            ks[cc][nn] = kb[off];
        }
        __syncthreads();
        #pragma unroll 8
        for (int n = 0; n < 64; n++) {
            float qv = qs[c][n];
            #pragma unroll
            for (int j = 0; j < 4; j++) acc[j] += qv * ks[d0+j][n];
        }
        if (sub == 0) {
            #pragma unroll 8
            for (int n = 0; n < 64; n++) { float v = qs[c][n]; ssq += v*v; }
        } else if (sub == 1) {
            #pragma unroll 8
            for (int n = 0; n < 64; n++) { float v = ks[c][n]; ssq += v*v; }
        }
        __syncthreads();
    }
    #pragma unroll
    for (int j = 0; j < 4; j++)
        atomicAdd(&g_gram[((size_t)bh*32 + c)*32 + d0 + j], acc[j]);
    if (sub == 0) atomicAdd(&g_qss[b*C_ + h*32 + c], ssq);
    else if (sub == 1) atomicAdd(&g_kss[b*C_ + h*32 + c], ssq);
}

__global__ __launch_bounds__(256) void softfold(const float* __restrict__ temp,
                                                const float* __restrict__ proj)
{
    int bh = blockIdx.x;
    int b = bh / HEADS, h = bh % HEADS;
    __shared__ float attn[32][33];
    __shared__ float iq[32], ik[32];
    int tid = threadIdx.x;
    int wrp = tid >> 5, ln = tid & 31;
    if (tid < 32)
        iq[tid] = 1.f / fmaxf(sqrtf(g_qss[b*C_ + h*32 + tid]), 1e-12f);
    else if (tid < 64)
        ik[tid-32] = 1.f / fmaxf(sqrtf(g_kss[b*C_ + h*32 + tid-32]), 1e-12f);
    __syncthreads();
    float tmp = temp[h];
    for (int r = wrp; r < 32; r += 8) {
        float v = g_gram[((size_t)bh*32 + r)*32 + ln] * iq[r] * ik[ln] * tmp;
        float m = v;
        #pragma unroll
        for (int off = 16; off; off >>= 1) m = fmaxf(m, __shfl_xor_sync(0xffffffff, m, off));
        float e = expf(v - m);
        float s = e;
        #pragma unroll
        for (int off = 16; off; off >>= 1) s += __shfl_xor_sync(0xffffffff, s, off);
        attn[r][ln] = e / s;
    }
    __syncthreads();
    for (int l = tid; l < C_*32; l += 256) {
        int co = l >> 5, d = l & 31;
        float s = 0.f;
        #pragma unroll
        for (int cc = 0; cc < 32; cc++)
            s += proj[(size_t)co*C_ + h*32 + cc] * attn[cc][d];
        g_weff[((size_t)b*C_ + co)*C_ + h*32 + d] = s;
    }
}

// ------------------ launcher ------------------
extern "C" void kernel_launch(void* const* d_in, const int* in_sizes, int n_in,
                              void* d_out, int out_size)
{
    const float* x           = (const float*)d_in[0];
    const float* y           = (const float*)d_in[1];
    const float* q_w         = (const float*)d_in[2];
    const float* kv_w        = (const float*)d_in[3];
    const float* kvdw_w      = (const float*)d_in[4];
    const float* proj_w      = (const float*)d_in[5];
    const float* temperature = (const float*)d_in[6];

    float *p_kv, *p_kvd, *p_q;
    __half *p_xh,*p_yh,*p_yl,*p_vh,*p_vl,*p_kvwh,*p_kvwl,*p_qwh,*p_wfh,*p_wfl;
    cudaGetSymbolAddress((void**)&p_kv, g_kv);   cudaGetSymbolAddress((void**)&p_kvd, g_kvd);
    cudaGetSymbolAddress((void**)&p_q, g_q);
    cudaGetSymbolAddress((void**)&p_xh, g_xh);
    cudaGetSymbolAddress((void**)&p_yh, g_yh);   cudaGetSymbolAddress((void**)&p_yl, g_yl);
    cudaGetSymbolAddress((void**)&p_vh, g_vh);   cudaGetSymbolAddress((void**)&p_vl, g_vl);
    cudaGetSymbolAddress((void**)&p_kvwh, g_kvwh); cudaGetSymbolAddress((void**)&p_kvwl, g_kvwl);
    cudaGetSymbolAddress((void**)&p_qwh, g_qwh);
    cudaGetSymbolAddress((void**)&p_wfh, g_wfh); cudaGetSymbolAddress((void**)&p_wfl, g_wfl);

    const int SM_T1 = 98304;    // 2 stages x (24576 A + 24576 B)
    const int SM_T3 = 196608;   // 2 stages x (49152 A + 49152 B)
    cudaFuncSetAttribute(hgemm<9,1>, cudaFuncAttributeMaxDynamicSharedMemorySize, SM_T1);
    cudaFuncSetAttribute(hgemm<1,1>, cudaFuncAttributeMaxDynamicSharedMemorySize, SM_T1);
    cudaFuncSetAttribute(hgemm<1,3>, cudaFuncAttributeMaxDynamicSharedMemorySize, SM_T3);

    dim3 tb(32,8);
    // prepack
    pack_kvw<<<(384*192+255)/256, 256>>>(kv_w, p_kvwh, p_kvwl);
    pack_qw <<<(192*9*192+255)/256, 256>>>(q_w, p_qwh);
    t32pad<<<dim3(HW_/32, C_/32, B_), tb>>>(x, p_xh);
    zb<<<(B_*772*C_+255)/256, 256>>>(p_xh);
    t32<<<dim3(HW_/32, C_/32, B_), tb>>>(y, (size_t)C_*HW_, p_yh, p_yl);

    // k = kv_w[0:192] @ y  (1-term fp16; error attenuated through softmax)
    hgemm<1,1><<<dim3(HW_/NT, B_), 384, SM_T1>>>(
        p_kvwh, nullptr, 0, p_yh, nullptr, (size_t)HW_*C_, (size_t)NT*C_,
        p_kv, (size_t)2*C_*HW_);

    // v = kv_w[192:384] @ y  (3-term: output is linear in v)
    hgemm<1,3><<<dim3(HW_/NT, B_), 384, SM_T3>>>(
        p_kvwh + (size_t)192*192, p_kvwl + (size_t)192*192, 0,
        p_yh, p_yl, (size_t)HW_*C_, (size_t)NT*C_,
        p_kv + (size_t)C_*HW_, (size_t)2*C_*HW_);

    // depthwise 3x3 -> g_kvd = [k|v]
    dwconv_t<<<dim3(H_/32, 2*C_, B_), 256>>>(p_kv, kvdw_w, p_kvd);

    // q = conv3x3(x) via 9 shifted GEMMs (1-term fp16)
    hgemm<9,1><<<dim3(H_, B_), 384, SM_T1>>>(
        p_qwh, nullptr, 0, p_xh, nullptr, (size_t)PW*PW*C_, (size_t)PW*C_,
        p_q, (size_t)C_*HW_);

    // v -> pixel-major fp16 hi/lo
    t32<<<dim3(HW_/32, C_/32, B_), tb>>>(p_kvd + (size_t)C_*HW_, (size_t)2*C_*HW_, p_vh, p_vl);

    // gram (+fused norms), softmax, fold proj
    zero_acc<<<(B_*HEADS*32*32 + 2*B_*C_ + 255)/256, 256>>>();
    gram_kernel<<<dim3(8, B_*HEADS), 256>>>(p_q, p_kvd);
    softfold<<<B_*HEADS, 256>>>(temperature, proj_w);
    pack_weff<<<(B_*192*192+255)/256, 256>>>(p_wfh, p_wfl);

    // out = W_eff[b](192x192) @ v[b]  (3-term)
    hgemm<1,3><<<dim3(HW_/NT, B_), 384, SM_T3>>>(
        p_wfh, p_wfl, (size_t)192*192, p_vh, p_vl, (size_t)HW_*C_, (size_t)NT*C_,
        (float*)d_out, (size_t)C_*HW_);
}